// round 1
// baseline (speedup 1.0000x reference)
#include <cuda_runtime.h>
#include <cuda_bf16.h>

// Problem constants
#define BB 4
#define SS 4096
#define DD 256
#define NN (BB*SS)   // 16384 rows

// Scratch (allocation-free rule: __device__ globals)
__device__ float g_Q[NN*DD];
__device__ float g_K[NN*DD];
__device__ float g_V[NN*DD];
__device__ float g_O[NN*DD];
__device__ unsigned char g_mask[NN];

// ---------------------------------------------------------------------------
// proj_kernel: C[n,m] = sum_e A[n,e]*W[m,e] + bias[m]
// A: [NN,256] row-major, W: [256,256] row-major (we multiply by W^T).
// 64x64 output tile, 256 threads, 4x4 micro-tile with strided column map.
// ---------------------------------------------------------------------------
__global__ __launch_bounds__(256) void proj_kernel(
    const float* __restrict__ A, const float* __restrict__ W,
    const float* __restrict__ bias, float* __restrict__ C)
{
    __shared__ float4 As[64*17];  // 64 rows x 16 f4 (=64 floats) + 1 f4 pad
    __shared__ float4 Ws[64*17];

    const int tid = threadIdx.x;
    const int ty = tid >> 4;      // 0..15
    const int tx = tid & 15;      // 0..15
    const int i0 = blockIdx.x * 64;
    const int j0 = blockIdx.y * 64;

    float acc[4][4] = {};

    const float4* A4 = reinterpret_cast<const float4*>(A) + (size_t)i0 * 64;
    const float4* W4 = reinterpret_cast<const float4*>(W) + (size_t)j0 * 64;

    // K = 256 floats = 64 f4, chunks of 16 f4
    for (int k0 = 0; k0 < 64; k0 += 16) {
        #pragma unroll
        for (int t = 0; t < 4; t++) {
            int idx = tid + t * 256;          // 0..1023
            int r  = idx >> 4;                // 0..63
            int e4 = idx & 15;                // 0..15
            As[r*17 + e4] = A4[(size_t)r*64 + k0 + e4];
            Ws[r*17 + e4] = W4[(size_t)r*64 + k0 + e4];
        }
        __syncthreads();

        #pragma unroll
        for (int e4 = 0; e4 < 16; e4++) {
            float4 a[4], w[4];
            #pragma unroll
            for (int r = 0; r < 4; r++) a[r] = As[(ty + 16*r)*17 + e4];
            #pragma unroll
            for (int c = 0; c < 4; c++) w[c] = Ws[(tx + 16*c)*17 + e4];
            #pragma unroll
            for (int r = 0; r < 4; r++)
                #pragma unroll
                for (int c = 0; c < 4; c++)
                    acc[r][c] += a[r].x*w[c].x + a[r].y*w[c].y
                               + a[r].z*w[c].z + a[r].w*w[c].w;
        }
        __syncthreads();
    }

    #pragma unroll
    for (int r = 0; r < 4; r++) {
        int n = i0 + ty + 16*r;
        #pragma unroll
        for (int c = 0; c < 4; c++) {
            int m = j0 + tx + 16*c;
            C[(size_t)n*DD + m] = acc[r][c] + bias[m];
        }
    }
}

// ---------------------------------------------------------------------------
// mask_kernel: row_mask[b,s] = (Q[b,s,0]!=0) && (K[b,s,0]!=0)
// ---------------------------------------------------------------------------
__global__ void mask_kernel(const float* __restrict__ Q,
                            const float* __restrict__ K,
                            unsigned char* __restrict__ M)
{
    int t = blockIdx.x * 256 + threadIdx.x;
    if (t < NN)
        M[t] = (Q[(size_t)t*DD] != 0.0f) && (K[(size_t)t*DD] != 0.0f);
}

// ---------------------------------------------------------------------------
// flash_kernel: online-softmax attention.
// Grid: (S/64, B). 256 threads. Per-CTA: 64 query rows, full D=256.
// Key tiles of 64 streamed; Q,K as padded float4 tiles, V row-major.
// Masked query rows zeroed at the epilogue (keys are never masked).
// ---------------------------------------------------------------------------
#define FL_SMEM_BYTES (64*65*16*2 /*Qs,Ks*/ + 64*64*16 /*Vs*/ \
                       + 64*68*4 /*Ps*/ + 3*64*4 /*m,l,alpha*/)

__global__ __launch_bounds__(256) void flash_kernel(
    const float* __restrict__ Qg_, const float* __restrict__ Kg_,
    const float* __restrict__ Vg_, const unsigned char* __restrict__ M,
    float* __restrict__ Out)
{
    extern __shared__ float4 sm4[];
    float4* Qs  = sm4;                 // 64 x 65 f4
    float4* Ks  = Qs + 64*65;          // 64 x 65 f4
    float4* Vs4 = Ks + 64*65;          // 64 x 64 f4 (row-major, no pad)
    float*  Vs  = reinterpret_cast<float*>(Vs4);
    float*  Ps  = reinterpret_cast<float*>(Vs4 + 64*64);  // 64 x 68 floats
    float*  mrow = Ps + 64*68;
    float*  lrow = mrow + 64;
    float*  arow = lrow + 64;

    const int tid = threadIdx.x;
    const int ty = tid >> 4;     // 0..15
    const int tx = tid & 15;     // 0..15
    const int b  = blockIdx.y;
    const int i0 = blockIdx.x * 64;

    const float4* Qg = reinterpret_cast<const float4*>(Qg_) + ((size_t)b*SS + i0) * 64;
    const float4* Kg = reinterpret_cast<const float4*>(Kg_) + (size_t)b*SS*64;
    const float4* Vg = reinterpret_cast<const float4*>(Vg_) + (size_t)b*SS*64;

    // Load Q tile: 64 rows x 64 f4
    #pragma unroll
    for (int t = 0; t < 16; t++) {
        int idx = tid + t * 256;
        int r  = idx >> 6;
        int e4 = idx & 63;
        Qs[r*65 + e4] = Qg[(size_t)r*64 + e4];
    }
    if (tid < 64) { mrow[tid] = -3.0e38f; lrow[tid] = 0.0f; }

    float o[4][16];
    #pragma unroll
    for (int r = 0; r < 4; r++)
        #pragma unroll
        for (int c = 0; c < 16; c++) o[r][c] = 0.0f;

    const float scale = 0.0625f;  // 1/sqrt(256)

    for (int kt = 0; kt < SS/64; kt++) {
        __syncthreads();  // previous GEMM2 done reading Ks/Vs/Ps; Qs visible on iter 0
        #pragma unroll
        for (int t = 0; t < 16; t++) {
            int idx = tid + t * 256;
            int r  = idx >> 6;
            int e4 = idx & 63;
            Ks[r*65 + e4]  = Kg[((size_t)(kt*64 + r))*64 + e4];
            Vs4[r*64 + e4] = Vg[((size_t)(kt*64 + r))*64 + e4];
        }
        __syncthreads();

        // ---- GEMM1: S = Q K^T (per-thread 4x4, strided i=ty+16r, j=tx+16c) ----
        float s[4][4] = {};
        #pragma unroll 4
        for (int e4 = 0; e4 < 64; e4++) {
            float4 q[4], k[4];
            #pragma unroll
            for (int r = 0; r < 4; r++) q[r] = Qs[(ty + 16*r)*65 + e4];
            #pragma unroll
            for (int c = 0; c < 4; c++) k[c] = Ks[(tx + 16*c)*65 + e4];
            #pragma unroll
            for (int r = 0; r < 4; r++)
                #pragma unroll
                for (int c = 0; c < 4; c++)
                    s[r][c] += q[r].x*k[c].x + q[r].y*k[c].y
                             + q[r].z*k[c].z + q[r].w*k[c].w;
        }
        #pragma unroll
        for (int r = 0; r < 4; r++)
            #pragma unroll
            for (int c = 0; c < 4; c++)
                Ps[(ty + 16*r)*68 + (tx + 16*c)] = s[r][c] * scale;
        __syncthreads();

        // ---- Online softmax: 4 threads per row, 16 cols each ----
        {
            int i = tid >> 2;
            int p = tid & 3;
            float vals[16];
            float mloc = -3.0e38f;
            #pragma unroll
            for (int c2 = 0; c2 < 16; c2++) {
                vals[c2] = Ps[i*68 + p*16 + c2];
                mloc = fmaxf(mloc, vals[c2]);
            }
            mloc = fmaxf(mloc, __shfl_xor_sync(0xffffffff, mloc, 1));
            mloc = fmaxf(mloc, __shfl_xor_sync(0xffffffff, mloc, 2));
            float mold = mrow[i];
            float mnew = fmaxf(mold, mloc);
            float lsum = 0.0f;
            #pragma unroll
            for (int c2 = 0; c2 < 16; c2++) {
                float e = __expf(vals[c2] - mnew);
                Ps[i*68 + p*16 + c2] = e;
                lsum += e;
            }
            lsum += __shfl_xor_sync(0xffffffff, lsum, 1);
            lsum += __shfl_xor_sync(0xffffffff, lsum, 2);
            if (p == 0) {
                float al = __expf(mold - mnew);
                arow[i] = al;
                lrow[i] = lrow[i] * al + lsum;
                mrow[i] = mnew;
            }
        }
        __syncthreads();

        // ---- Rescale O, then GEMM2: O += P V  (cols d = tx+16c) ----
        float al[4];
        #pragma unroll
        for (int r = 0; r < 4; r++) al[r] = arow[ty + 16*r];
        #pragma unroll
        for (int r = 0; r < 4; r++)
            #pragma unroll
            for (int c = 0; c < 16; c++) o[r][c] *= al[r];

        #pragma unroll 4
        for (int j = 0; j < 64; j++) {
            float pr[4];
            #pragma unroll
            for (int r = 0; r < 4; r++) pr[r] = Ps[(ty + 16*r)*68 + j];
            #pragma unroll
            for (int c = 0; c < 16; c++) {
                float v = Vs[j*256 + tx + 16*c];
                #pragma unroll
                for (int r = 0; r < 4; r++) o[r][c] += pr[r] * v;
            }
        }
    }

    // Epilogue: normalize by l, apply row mask (masked rows -> 0)
    #pragma unroll
    for (int r = 0; r < 4; r++) {
        int i = ty + 16*r;
        float inv = 1.0f / lrow[i];
        float mf = M[(size_t)b*SS + i0 + i] ? inv : 0.0f;
        #pragma unroll
        for (int c = 0; c < 16; c++) {
            Out[((size_t)(b*SS + i0 + i))*DD + tx + 16*c] = o[r][c] * mf;
        }
    }
}

// ---------------------------------------------------------------------------
// Launch: QKV projections -> mask -> flash attention -> output projection.
// All on default stream, graph-capturable, no allocations.
// ---------------------------------------------------------------------------
extern "C" void kernel_launch(void* const* d_in, const int* in_sizes, int n_in,
                              void* d_out, int out_size)
{
    const float* src = (const float*)d_in[0];
    const float* Wq  = (const float*)d_in[1];
    const float* bq  = (const float*)d_in[2];
    const float* Wk  = (const float*)d_in[3];
    const float* bk  = (const float*)d_in[4];
    const float* Wv  = (const float*)d_in[5];
    const float* bv  = (const float*)d_in[6];
    const float* Wo  = (const float*)d_in[7];
    const float* bo  = (const float*)d_in[8];
    float* out = (float*)d_out;

    float *pQ, *pK, *pV, *pO;
    unsigned char* pM;
    cudaGetSymbolAddress((void**)&pQ, g_Q);
    cudaGetSymbolAddress((void**)&pK, g_K);
    cudaGetSymbolAddress((void**)&pV, g_V);
    cudaGetSymbolAddress((void**)&pO, g_O);
    cudaGetSymbolAddress((void**)&pM, g_mask);

    dim3 pg(NN/64, DD/64);  // 256 x 4
    proj_kernel<<<pg, 256>>>(src, Wq, bq, pQ);
    proj_kernel<<<pg, 256>>>(src, Wk, bk, pK);
    proj_kernel<<<pg, 256>>>(src, Wv, bv, pV);

    mask_kernel<<<NN/256, 256>>>(pQ, pK, pM);

    cudaFuncSetAttribute(flash_kernel,
                         cudaFuncAttributeMaxDynamicSharedMemorySize,
                         FL_SMEM_BYTES);
    flash_kernel<<<dim3(SS/64, BB), 256, FL_SMEM_BYTES>>>(pQ, pK, pV, pM, pO);

    proj_kernel<<<pg, 256>>>(pO, Wo, bo, out);
}

// round 2
// speedup vs baseline: 1.0015x; 1.0015x over previous
#include <cuda_runtime.h>
#include <cuda_bf16.h>

// Problem constants
#define BB 4
#define SS 4096
#define DD 256
#define NN (BB*SS)   // 16384 rows

// Scratch (allocation-free rule: __device__ globals)
__device__ float g_Q[NN*DD];
__device__ float g_K[NN*DD];
__device__ float g_V[NN*DD];
__device__ float g_O[NN*DD];
__device__ unsigned char g_mask[NN];

// ---------------------------------------------------------------------------
// proj_kernel: C[n,m] = sum_e A[n,e]*W[m,e] + bias[m]
// A: [NN,256] row-major, W: [256,256] row-major (we multiply by W^T).
// 64x64 output tile, 256 threads, 4x4 micro-tile with strided column map.
// ---------------------------------------------------------------------------
__global__ __launch_bounds__(256) void proj_kernel(
    const float* __restrict__ A, const float* __restrict__ W,
    const float* __restrict__ bias, float* __restrict__ C)
{
    __shared__ float4 As[64*17];  // 64 rows x 16 f4 (=64 floats) + 1 f4 pad
    __shared__ float4 Ws[64*17];

    const int tid = threadIdx.x;
    const int ty = tid >> 4;      // 0..15
    const int tx = tid & 15;      // 0..15
    const int i0 = blockIdx.x * 64;
    const int j0 = blockIdx.y * 64;

    float acc[4][4] = {};

    const float4* A4 = reinterpret_cast<const float4*>(A) + (size_t)i0 * 64;
    const float4* W4 = reinterpret_cast<const float4*>(W) + (size_t)j0 * 64;

    // K = 256 floats = 64 f4, chunks of 16 f4
    for (int k0 = 0; k0 < 64; k0 += 16) {
        #pragma unroll
        for (int t = 0; t < 4; t++) {
            int idx = tid + t * 256;          // 0..1023
            int r  = idx >> 4;                // 0..63
            int e4 = idx & 15;                // 0..15
            As[r*17 + e4] = A4[(size_t)r*64 + k0 + e4];
            Ws[r*17 + e4] = W4[(size_t)r*64 + k0 + e4];
        }
        __syncthreads();

        #pragma unroll
        for (int e4 = 0; e4 < 16; e4++) {
            float4 a[4], w[4];
            #pragma unroll
            for (int r = 0; r < 4; r++) a[r] = As[(ty + 16*r)*17 + e4];
            #pragma unroll
            for (int c = 0; c < 4; c++) w[c] = Ws[(tx + 16*c)*17 + e4];
            #pragma unroll
            for (int r = 0; r < 4; r++)
                #pragma unroll
                for (int c = 0; c < 4; c++)
                    acc[r][c] += a[r].x*w[c].x + a[r].y*w[c].y
                               + a[r].z*w[c].z + a[r].w*w[c].w;
        }
        __syncthreads();
    }

    #pragma unroll
    for (int r = 0; r < 4; r++) {
        int n = i0 + ty + 16*r;
        #pragma unroll
        for (int c = 0; c < 4; c++) {
            int m = j0 + tx + 16*c;
            C[(size_t)n*DD + m] = acc[r][c] + bias[m];
        }
    }
}

// ---------------------------------------------------------------------------
// mask_kernel: row_mask[b,s] = (Q[b,s,0]!=0) && (K[b,s,0]!=0)
// ---------------------------------------------------------------------------
__global__ void mask_kernel(const float* __restrict__ Q,
                            const float* __restrict__ K,
                            unsigned char* __restrict__ M)
{
    int t = blockIdx.x * 256 + threadIdx.x;
    if (t < NN)
        M[t] = (Q[(size_t)t*DD] != 0.0f) && (K[(size_t)t*DD] != 0.0f);
}

// ---------------------------------------------------------------------------
// flash_kernel: online-softmax attention.
// Grid: (S/64, B). 256 threads. Per-CTA: 64 query rows, full D=256.
// Key tiles of 64 streamed; Q,K as padded float4 tiles, V row-major.
// Masked query rows zeroed at the epilogue (keys are never masked).
// ---------------------------------------------------------------------------
#define FL_SMEM_BYTES (64*65*16*2 /*Qs,Ks*/ + 64*64*16 /*Vs*/ \
                       + 64*68*4 /*Ps*/ + 3*64*4 /*m,l,alpha*/)

__global__ __launch_bounds__(256) void flash_kernel(
    const float* __restrict__ Qg_, const float* __restrict__ Kg_,
    const float* __restrict__ Vg_, const unsigned char* __restrict__ M,
    float* __restrict__ Out)
{
    extern __shared__ float4 sm4[];
    float4* Qs  = sm4;                 // 64 x 65 f4
    float4* Ks  = Qs + 64*65;          // 64 x 65 f4
    float4* Vs4 = Ks + 64*65;          // 64 x 64 f4 (row-major, no pad)
    float*  Vs  = reinterpret_cast<float*>(Vs4);
    float*  Ps  = reinterpret_cast<float*>(Vs4 + 64*64);  // 64 x 68 floats
    float*  mrow = Ps + 64*68;
    float*  lrow = mrow + 64;
    float*  arow = lrow + 64;

    const int tid = threadIdx.x;
    const int ty = tid >> 4;     // 0..15
    const int tx = tid & 15;     // 0..15
    const int b  = blockIdx.y;
    const int i0 = blockIdx.x * 64;

    const float4* Qg = reinterpret_cast<const float4*>(Qg_) + ((size_t)b*SS + i0) * 64;
    const float4* Kg = reinterpret_cast<const float4*>(Kg_) + (size_t)b*SS*64;
    const float4* Vg = reinterpret_cast<const float4*>(Vg_) + (size_t)b*SS*64;

    // Load Q tile: 64 rows x 64 f4
    #pragma unroll
    for (int t = 0; t < 16; t++) {
        int idx = tid + t * 256;
        int r  = idx >> 6;
        int e4 = idx & 63;
        Qs[r*65 + e4] = Qg[(size_t)r*64 + e4];
    }
    if (tid < 64) { mrow[tid] = -3.0e38f; lrow[tid] = 0.0f; }

    float o[4][16];
    #pragma unroll
    for (int r = 0; r < 4; r++)
        #pragma unroll
        for (int c = 0; c < 16; c++) o[r][c] = 0.0f;

    const float scale = 0.0625f;  // 1/sqrt(256)

    for (int kt = 0; kt < SS/64; kt++) {
        __syncthreads();  // previous GEMM2 done reading Ks/Vs/Ps; Qs visible on iter 0
        #pragma unroll
        for (int t = 0; t < 16; t++) {
            int idx = tid + t * 256;
            int r  = idx >> 6;
            int e4 = idx & 63;
            Ks[r*65 + e4]  = Kg[((size_t)(kt*64 + r))*64 + e4];
            Vs4[r*64 + e4] = Vg[((size_t)(kt*64 + r))*64 + e4];
        }
        __syncthreads();

        // ---- GEMM1: S = Q K^T (per-thread 4x4, strided i=ty+16r, j=tx+16c) ----
        float s[4][4] = {};
        #pragma unroll 4
        for (int e4 = 0; e4 < 64; e4++) {
            float4 q[4], k[4];
            #pragma unroll
            for (int r = 0; r < 4; r++) q[r] = Qs[(ty + 16*r)*65 + e4];
            #pragma unroll
            for (int c = 0; c < 4; c++) k[c] = Ks[(tx + 16*c)*65 + e4];
            #pragma unroll
            for (int r = 0; r < 4; r++)
                #pragma unroll
                for (int c = 0; c < 4; c++)
                    s[r][c] += q[r].x*k[c].x + q[r].y*k[c].y
                             + q[r].z*k[c].z + q[r].w*k[c].w;
        }
        #pragma unroll
        for (int r = 0; r < 4; r++)
            #pragma unroll
            for (int c = 0; c < 4; c++)
                Ps[(ty + 16*r)*68 + (tx + 16*c)] = s[r][c] * scale;
        __syncthreads();

        // ---- Online softmax: 4 threads per row, 16 cols each ----
        {
            int i = tid >> 2;
            int p = tid & 3;
            float vals[16];
            float mloc = -3.0e38f;
            #pragma unroll
            for (int c2 = 0; c2 < 16; c2++) {
                vals[c2] = Ps[i*68 + p*16 + c2];
                mloc = fmaxf(mloc, vals[c2]);
            }
            mloc = fmaxf(mloc, __shfl_xor_sync(0xffffffff, mloc, 1));
            mloc = fmaxf(mloc, __shfl_xor_sync(0xffffffff, mloc, 2));
            float mold = mrow[i];
            float mnew = fmaxf(mold, mloc);
            float lsum = 0.0f;
            #pragma unroll
            for (int c2 = 0; c2 < 16; c2++) {
                float e = __expf(vals[c2] - mnew);
                Ps[i*68 + p*16 + c2] = e;
                lsum += e;
            }
            lsum += __shfl_xor_sync(0xffffffff, lsum, 1);
            lsum += __shfl_xor_sync(0xffffffff, lsum, 2);
            if (p == 0) {
                float al = __expf(mold - mnew);
                arow[i] = al;
                lrow[i] = lrow[i] * al + lsum;
                mrow[i] = mnew;
            }
        }
        __syncthreads();

        // ---- Rescale O, then GEMM2: O += P V  (cols d = tx+16c) ----
        float al[4];
        #pragma unroll
        for (int r = 0; r < 4; r++) al[r] = arow[ty + 16*r];
        #pragma unroll
        for (int r = 0; r < 4; r++)
            #pragma unroll
            for (int c = 0; c < 16; c++) o[r][c] *= al[r];

        #pragma unroll 4
        for (int j = 0; j < 64; j++) {
            float pr[4];
            #pragma unroll
            for (int r = 0; r < 4; r++) pr[r] = Ps[(ty + 16*r)*68 + j];
            #pragma unroll
            for (int c = 0; c < 16; c++) {
                float v = Vs[j*256 + tx + 16*c];
                #pragma unroll
                for (int r = 0; r < 4; r++) o[r][c] += pr[r] * v;
            }
        }
    }

    // Epilogue: normalize by l, apply row mask (masked rows -> 0)
    #pragma unroll
    for (int r = 0; r < 4; r++) {
        int i = ty + 16*r;
        float inv = 1.0f / lrow[i];
        float mf = M[(size_t)b*SS + i0 + i] ? inv : 0.0f;
        #pragma unroll
        for (int c = 0; c < 16; c++) {
            Out[((size_t)(b*SS + i0 + i))*DD + tx + 16*c] = o[r][c] * mf;
        }
    }
}

// ---------------------------------------------------------------------------
// Launch: QKV projections -> mask -> flash attention -> output projection.
// All on default stream, graph-capturable, no allocations.
// ---------------------------------------------------------------------------
extern "C" void kernel_launch(void* const* d_in, const int* in_sizes, int n_in,
                              void* d_out, int out_size)
{
    const float* src = (const float*)d_in[0];
    const float* Wq  = (const float*)d_in[1];
    const float* bq  = (const float*)d_in[2];
    const float* Wk  = (const float*)d_in[3];
    const float* bk  = (const float*)d_in[4];
    const float* Wv  = (const float*)d_in[5];
    const float* bv  = (const float*)d_in[6];
    const float* Wo  = (const float*)d_in[7];
    const float* bo  = (const float*)d_in[8];
    float* out = (float*)d_out;

    float *pQ, *pK, *pV, *pO;
    unsigned char* pM;
    cudaGetSymbolAddress((void**)&pQ, g_Q);
    cudaGetSymbolAddress((void**)&pK, g_K);
    cudaGetSymbolAddress((void**)&pV, g_V);
    cudaGetSymbolAddress((void**)&pO, g_O);
    cudaGetSymbolAddress((void**)&pM, g_mask);

    dim3 pg(NN/64, DD/64);  // 256 x 4
    proj_kernel<<<pg, 256>>>(src, Wq, bq, pQ);
    proj_kernel<<<pg, 256>>>(src, Wk, bk, pK);
    proj_kernel<<<pg, 256>>>(src, Wv, bv, pV);

    mask_kernel<<<NN/256, 256>>>(pQ, pK, pM);

    cudaFuncSetAttribute(flash_kernel,
                         cudaFuncAttributeMaxDynamicSharedMemorySize,
                         FL_SMEM_BYTES);
    flash_kernel<<<dim3(SS/64, BB), 256, FL_SMEM_BYTES>>>(pQ, pK, pV, pM, pO);

    proj_kernel<<<pg, 256>>>(pO, Wo, bo, out);
}

// round 4
// speedup vs baseline: 1.8976x; 1.8948x over previous
#include <cuda_runtime.h>
#include <cuda_fp16.h>
#include <cstdint>

#define BB 4
#define SS 4096
#define DD 256
#define NN (BB*SS)

// ---------------- device scratch ----------------
__device__ __half g_Qhi[NN*DD];
__device__ __half g_Qlo[NN*DD];
__device__ __half g_Khi[NN*DD];
__device__ __half g_Klo[NN*DD];
__device__ __half g_Vthi[NN*DD];   // [b][d][s]
__device__ __half g_Vtlo[NN*DD];
__device__ float g_q0[NN];
__device__ float g_k0[NN];
__device__ float g_O[NN*DD];

// ---------------- helpers ----------------
#define SWZ(o) ((o) ^ (((o) >> 3) & 0x70))

__device__ __forceinline__ uint32_t smem_u32(const void* p){
    uint32_t a;
    asm("{ .reg .u64 t; cvta.to.shared.u64 t, %1; cvt.u32.u64 %0, t; }" : "=r"(a) : "l"(p));
    return a;
}
__device__ __forceinline__ void sts128(uint32_t a, uint4 v){
    asm volatile("st.shared.v4.b32 [%0], {%1,%2,%3,%4};"
                 :: "r"(a), "r"(v.x), "r"(v.y), "r"(v.z), "r"(v.w) : "memory");
}
__device__ __forceinline__ void sts32(uint32_t a, uint32_t v){
    asm volatile("st.shared.b32 [%0], %1;" :: "r"(a), "r"(v) : "memory");
}
#define LDMX4(d0,d1,d2,d3,a) \
    asm volatile("ldmatrix.sync.aligned.m8n8.x4.shared.b16 {%0,%1,%2,%3}, [%4];" \
                 : "=r"(d0),"=r"(d1),"=r"(d2),"=r"(d3) : "r"(a))
#define MMA16816(c,a0,a1,a2,a3,b0,b1) \
    asm volatile("mma.sync.aligned.m16n8k16.row.col.f32.f16.f16.f32 " \
                 "{%0,%1,%2,%3},{%4,%5,%6,%7},{%8,%9},{%0,%1,%2,%3};" \
                 : "+f"((c)[0]),"+f"((c)[1]),"+f"((c)[2]),"+f"((c)[3]) \
                 : "r"(a0),"r"(a1),"r"(a2),"r"(a3),"r"(b0),"r"(b1))

// blocked-atom swizzled smem address of 16B chunk (r, c16); apg = atoms per 8-row group
__device__ __forceinline__ uint32_t tadr(uint32_t base, int r, int c16, int apg){
    return base + (uint32_t)(((((r>>3)*apg + (c16>>3))<<10)) +
                             SWZ((uint32_t)(((r&7)<<7) | ((c16&7)<<4))));
}

__device__ __forceinline__ void hsplit(float x, uint32_t& h, uint32_t& l){
    __half hh = __float2half_rn(x);
    __half hl = __float2half_rn(x - __half2float(hh));
    h = (uint32_t)__half_as_ushort(hh);
    l = (uint32_t)__half_as_ushort(hl);
}

// ---------------------------------------------------------------------------
// proj_qk: C = A W^T + b -> fp16 hi/lo (scaled); col0 fp32 saved for mask
// ---------------------------------------------------------------------------
__global__ __launch_bounds__(256) void proj_qk_kernel(
    const float* __restrict__ A, const float* __restrict__ W,
    const float* __restrict__ bias,
    __half* __restrict__ Chi, __half* __restrict__ Clo,
    float* __restrict__ col0, float scale)
{
    __shared__ float4 As[64*17];
    __shared__ float4 Ws[64*17];
    const int tid = threadIdx.x, ty = tid >> 4, tx = tid & 15;
    const int i0 = blockIdx.x * 64, j0 = blockIdx.y * 64;
    float acc[4][4] = {};
    const float4* A4 = reinterpret_cast<const float4*>(A) + (size_t)i0 * 64;
    const float4* W4 = reinterpret_cast<const float4*>(W) + (size_t)j0 * 64;
    for (int k0 = 0; k0 < 64; k0 += 16) {
        #pragma unroll
        for (int t = 0; t < 4; t++) {
            int idx = tid + t * 256, r = idx >> 4, e4 = idx & 15;
            As[r*17 + e4] = A4[(size_t)r*64 + k0 + e4];
            Ws[r*17 + e4] = W4[(size_t)r*64 + k0 + e4];
        }
        __syncthreads();
        #pragma unroll
        for (int e4 = 0; e4 < 16; e4++) {
            float4 a[4], w[4];
            #pragma unroll
            for (int r = 0; r < 4; r++) a[r] = As[(ty + 16*r)*17 + e4];
            #pragma unroll
            for (int c = 0; c < 4; c++) w[c] = Ws[(tx + 16*c)*17 + e4];
            #pragma unroll
            for (int r = 0; r < 4; r++)
                #pragma unroll
                for (int c = 0; c < 4; c++)
                    acc[r][c] += a[r].x*w[c].x + a[r].y*w[c].y + a[r].z*w[c].z + a[r].w*w[c].w;
        }
        __syncthreads();
    }
    #pragma unroll
    for (int r = 0; r < 4; r++) {
        int n = i0 + ty + 16*r;
        #pragma unroll
        for (int c = 0; c < 4; c++) {
            int m = j0 + tx + 16*c;
            float val = acc[r][c] + bias[m];
            if (m == 0) col0[n] = val;
            uint32_t h, l;
            hsplit(val * scale, h, l);
            Chi[(size_t)n*DD + m] = __ushort_as_half((unsigned short)h);
            Clo[(size_t)n*DD + m] = __ushort_as_half((unsigned short)l);
        }
    }
}

// ---------------------------------------------------------------------------
// proj_vt: V = A Wv^T + b -> transposed fp16 hi/lo [b][d][s]
// ---------------------------------------------------------------------------
__global__ __launch_bounds__(256) void proj_vt_kernel(
    const float* __restrict__ A, const float* __restrict__ W,
    const float* __restrict__ bias,
    __half* __restrict__ Vthi, __half* __restrict__ Vtlo)
{
    __shared__ float4 As[64*17];
    __shared__ float4 Ws[64*17];
    const int tid = threadIdx.x, ty = tid >> 4, tx = tid & 15;
    const int i0 = blockIdx.x * 64, j0 = blockIdx.y * 64;
    float acc[4][4] = {};
    const float4* A4 = reinterpret_cast<const float4*>(A) + (size_t)i0 * 64;
    const float4* W4 = reinterpret_cast<const float4*>(W) + (size_t)j0 * 64;
    for (int k0 = 0; k0 < 64; k0 += 16) {
        #pragma unroll
        for (int t = 0; t < 4; t++) {
            int idx = tid + t * 256, r = idx >> 4, e4 = idx & 15;
            As[r*17 + e4] = A4[(size_t)r*64 + k0 + e4];
            Ws[r*17 + e4] = W4[(size_t)r*64 + k0 + e4];
        }
        __syncthreads();
        #pragma unroll
        for (int e4 = 0; e4 < 16; e4++) {
            float4 a[4], w[4];
            #pragma unroll
            for (int r = 0; r < 4; r++) a[r] = As[(ty + 16*r)*17 + e4];
            #pragma unroll
            for (int c = 0; c < 4; c++) w[c] = Ws[(tx + 16*c)*17 + e4];
            #pragma unroll
            for (int r = 0; r < 4; r++)
                #pragma unroll
                for (int c = 0; c < 4; c++)
                    acc[r][c] += a[r].x*w[c].x + a[r].y*w[c].y + a[r].z*w[c].z + a[r].w*w[c].w;
        }
        __syncthreads();
    }
    float* st = reinterpret_cast<float*>(As);   // [s_local][d_local] 64x65
    #pragma unroll
    for (int r = 0; r < 4; r++)
        #pragma unroll
        for (int c = 0; c < 4; c++)
            st[(ty + 16*r)*65 + (tx + 16*c)] = acc[r][c] + bias[j0 + tx + 16*c];
    __syncthreads();

    const int b = i0 >> 12, s0 = i0 & 4095;
    uint4* Vh4 = reinterpret_cast<uint4*>(Vthi);
    uint4* Vl4 = reinterpret_cast<uint4*>(Vtlo);
    #pragma unroll
    for (int t = 0; t < 2; t++) {
        int idx = tid + t * 256;           // 0..511
        int dl = idx >> 3, ch = idx & 7;
        uint32_t hh[4], ll[4];
        #pragma unroll
        for (int e2 = 0; e2 < 4; e2++) {
            float v0 = st[(ch*8 + 2*e2    )*65 + dl];
            float v1 = st[(ch*8 + 2*e2 + 1)*65 + dl];
            uint32_t h0, l0, h1, l1;
            hsplit(v0, h0, l0); hsplit(v1, h1, l1);
            hh[e2] = h0 | (h1 << 16);
            ll[e2] = l0 | (l1 << 16);
        }
        size_t oidx = ((size_t)b*DD + j0 + dl)*512 + (s0 >> 3) + ch;
        Vh4[oidx] = make_uint4(hh[0], hh[1], hh[2], hh[3]);
        Vl4[oidx] = make_uint4(ll[0], ll[1], ll[2], ll[3]);
    }
}

// ---------------------------------------------------------------------------
// proj (fp32 out) — final Wo projection
// ---------------------------------------------------------------------------
__global__ __launch_bounds__(256) void proj_kernel(
    const float* __restrict__ A, const float* __restrict__ W,
    const float* __restrict__ bias, float* __restrict__ C)
{
    __shared__ float4 As[64*17];
    __shared__ float4 Ws[64*17];
    const int tid = threadIdx.x, ty = tid >> 4, tx = tid & 15;
    const int i0 = blockIdx.x * 64, j0 = blockIdx.y * 64;
    float acc[4][4] = {};
    const float4* A4 = reinterpret_cast<const float4*>(A) + (size_t)i0 * 64;
    const float4* W4 = reinterpret_cast<const float4*>(W) + (size_t)j0 * 64;
    for (int k0 = 0; k0 < 64; k0 += 16) {
        #pragma unroll
        for (int t = 0; t < 4; t++) {
            int idx = tid + t * 256, r = idx >> 4, e4 = idx & 15;
            As[r*17 + e4] = A4[(size_t)r*64 + k0 + e4];
            Ws[r*17 + e4] = W4[(size_t)r*64 + k0 + e4];
        }
        __syncthreads();
        #pragma unroll
        for (int e4 = 0; e4 < 16; e4++) {
            float4 a[4], w[4];
            #pragma unroll
            for (int r = 0; r < 4; r++) a[r] = As[(ty + 16*r)*17 + e4];
            #pragma unroll
            for (int c = 0; c < 4; c++) w[c] = Ws[(tx + 16*c)*17 + e4];
            #pragma unroll
            for (int r = 0; r < 4; r++)
                #pragma unroll
                for (int c = 0; c < 4; c++)
                    acc[r][c] += a[r].x*w[c].x + a[r].y*w[c].y + a[r].z*w[c].z + a[r].w*w[c].w;
        }
        __syncthreads();
    }
    #pragma unroll
    for (int r = 0; r < 4; r++) {
        int n = i0 + ty + 16*r;
        #pragma unroll
        for (int c = 0; c < 4; c++)
            C[(size_t)n*DD + j0 + tx + 16*c] = acc[r][c] + bias[j0 + tx + 16*c];
    }
}

// ---------------------------------------------------------------------------
// flash_mma: warp-level mma.sync flash attention, fp16 hi/lo split (3 MMAs).
// 128 queries/CTA, 8 warps x 16-row strips, 64-key tiles, O in registers.
// SMEM: Qhi 64K | Qlo 64K | KV hi 32K | KV lo 32K | Phi 16K | Plo 16K = 224K
// ---------------------------------------------------------------------------
#define OFF_QHI   0u
#define OFF_QLO   65536u
#define OFF_KVH   131072u
#define OFF_KVL   163840u
#define OFF_PHI   196608u
#define OFF_PLO   212992u
#define FL_SMEM   (229376 + 1024)

__global__ __launch_bounds__(256, 1) void flash_mma(
    const __half* __restrict__ Qhi_, const __half* __restrict__ Qlo_,
    const __half* __restrict__ Khi_, const __half* __restrict__ Klo_,
    const __half* __restrict__ Vthi_, const __half* __restrict__ Vtlo_,
    const float* __restrict__ q0g, const float* __restrict__ k0g,
    float* __restrict__ Out)
{
    extern __shared__ char fsm[];
    const uint32_t abase = (smem_u32(fsm) + 1023u) & ~1023u;
    const uint32_t aQh = abase + OFF_QHI, aQl = abase + OFF_QLO;
    const uint32_t aKh = abase + OFF_KVH, aKl = abase + OFF_KVL;
    const uint32_t aPh = abase + OFF_PHI, aPl = abase + OFF_PLO;

    const int tid = threadIdx.x, wid = tid >> 5, lane = tid & 31;
    const int b = blockIdx.y, i0 = blockIdx.x * 128;
    const int warp_m = wid * 16;

    // ldmatrix lane addressing
    const int mat = lane >> 3, lr = lane & 7;
    const int arow = (mat & 1) * 8 + lr;   // A: mat0/2 -> rows 0-7, mat1/3 -> 8-15
    const int asel = mat >> 1;             // A: mat0/1 -> k-chunk 0, mat2/3 -> 1
    const int brow = ((mat >> 1) << 3) + lr; // B: mat0/1 -> n 0-7, mat2/3 -> 8-15
    const int bsel = mat & 1;              // B: mat0/2 -> k-chunk 0, mat1/3 -> 1

    // ---- load Q tile (128 x 256 halves, hi+lo) ----
    {
        const uint4* Qh4 = reinterpret_cast<const uint4*>(Qhi_) + ((size_t)(b*SS + i0)) * 32;
        const uint4* Ql4 = reinterpret_cast<const uint4*>(Qlo_) + ((size_t)(b*SS + i0)) * 32;
        #pragma unroll
        for (int t = 0; t < 16; t++) {
            int idx = tid + t * 256;       // 0..4095
            int r = idx >> 5, c16 = idx & 31;
            sts128(tadr(aQh, r, c16, 4), Qh4[(size_t)r*32 + c16]);
            sts128(tadr(aQl, r, c16, 4), Ql4[(size_t)r*32 + c16]);
        }
    }

    const uint4* Kh4 = reinterpret_cast<const uint4*>(Khi_) + (size_t)b*SS*32;
    const uint4* Kl4 = reinterpret_cast<const uint4*>(Klo_) + (size_t)b*SS*32;
    const uint4* Vh4 = reinterpret_cast<const uint4*>(Vthi_) + (size_t)b*DD*512;
    const uint4* Vl4 = reinterpret_cast<const uint4*>(Vtlo_) + (size_t)b*DD*512;

    float oacc[32][4];
    #pragma unroll
    for (int i = 0; i < 32; i++)
        #pragma unroll
        for (int j = 0; j < 4; j++) oacc[i][j] = 0.0f;
    float lsum0 = 0.0f, lsum1 = 0.0f;

    for (int kt = 0; kt < SS/64; kt++) {
        __syncthreads();   // prev MMA2 done reading KV buffer
        // ---- K tile: 64 rows x 32 chunks, hi+lo ----
        #pragma unroll
        for (int t = 0; t < 8; t++) {
            int idx = tid + t * 256;       // 0..2047
            int r = idx >> 5, c16 = idx & 31;
            size_t gi = (size_t)(kt*64 + r)*32 + c16;
            sts128(tadr(aKh, r, c16, 4), Kh4[gi]);
            sts128(tadr(aKl, r, c16, 4), Kl4[gi]);
        }
        __syncthreads();

        // ---- MMA1: S = Q K^T ----
        float sacc[8][4];
        #pragma unroll
        for (int i = 0; i < 8; i++)
            #pragma unroll
            for (int j = 0; j < 4; j++) sacc[i][j] = 0.0f;

        #pragma unroll 4
        for (int ks = 0; ks < 16; ks++) {
            uint32_t ah0,ah1,ah2,ah3, al0,al1,al2,al3;
            LDMX4(ah0,ah1,ah2,ah3, tadr(aQh, warp_m + arow, 2*ks + asel, 4));
            LDMX4(al0,al1,al2,al3, tadr(aQl, warp_m + arow, 2*ks + asel, 4));
            #pragma unroll
            for (int np = 0; np < 4; np++) {
                uint32_t bh0,bh1,bh2,bh3, bl0,bl1,bl2,bl3;
                LDMX4(bh0,bh1,bh2,bh3, tadr(aKh, np*16 + brow, 2*ks + bsel, 4));
                LDMX4(bl0,bl1,bl2,bl3, tadr(aKl, np*16 + brow, 2*ks + bsel, 4));
                MMA16816(sacc[2*np  ], ah0,ah1,ah2,ah3, bh0,bh1);
                MMA16816(sacc[2*np  ], ah0,ah1,ah2,ah3, bl0,bl1);
                MMA16816(sacc[2*np  ], al0,al1,al2,al3, bh0,bh1);
                MMA16816(sacc[2*np+1], ah0,ah1,ah2,ah3, bh2,bh3);
                MMA16816(sacc[2*np+1], ah0,ah1,ah2,ah3, bl2,bl3);
                MMA16816(sacc[2*np+1], al0,al1,al2,al3, bh2,bh3);
            }
        }
        __syncthreads();   // all warps done reading K from KV buffer

        // ---- V^T tile: 256 rows(d) x 8 chunks(keys), hi+lo (overwrite KV) ----
        #pragma unroll
        for (int t = 0; t < 8; t++) {
            int idx = tid + t * 256;       // 0..2047
            int r = idx >> 3, c16 = idx & 7;
            size_t gi = (size_t)r*512 + (size_t)kt*8 + c16;
            sts128(tadr(aKh, r, c16, 1), Vh4[gi]);
            sts128(tadr(aKl, r, c16, 1), Vl4[gi]);
        }

        // ---- softmax (no max-sub) + P hi/lo to smem ----
        {
            int r0 = warp_m + (lane >> 2);
            int ib = (lane & 3) * 4;       // byte offset within 16B chunk
            #pragma unroll
            for (int nf = 0; nf < 8; nf++) {
                float e0 = __expf(sacc[nf][0]);
                float e1 = __expf(sacc[nf][1]);
                float e2 = __expf(sacc[nf][2]);
                float e3 = __expf(sacc[nf][3]);
                lsum0 += e0 + e1;
                lsum1 += e2 + e3;
                uint32_t h0,l0,h1,l1,h2,l2,h3,l3;
                hsplit(e0,h0,l0); hsplit(e1,h1,l1);
                hsplit(e2,h2,l2); hsplit(e3,h3,l3);
                sts32(tadr(aPh, r0,     nf, 1) + ib, h0 | (h1 << 16));
                sts32(tadr(aPl, r0,     nf, 1) + ib, l0 | (l1 << 16));
                sts32(tadr(aPh, r0 + 8, nf, 1) + ib, h2 | (h3 << 16));
                sts32(tadr(aPl, r0 + 8, nf, 1) + ib, l2 | (l3 << 16));
            }
        }
        __syncthreads();   // V + P visible

        // ---- MMA2: O += P V ----
        #pragma unroll
        for (int ks = 0; ks < 4; ks++) {
            uint32_t ah0,ah1,ah2,ah3, al0,al1,al2,al3;
            LDMX4(ah0,ah1,ah2,ah3, tadr(aPh, warp_m + arow, 2*ks + asel, 1));
            LDMX4(al0,al1,al2,al3, tadr(aPl, warp_m + arow, 2*ks + asel, 1));
            #pragma unroll 8
            for (int np = 0; np < 16; np++) {
                uint32_t bh0,bh1,bh2,bh3, bl0,bl1,bl2,bl3;
                LDMX4(bh0,bh1,bh2,bh3, tadr(aKh, np*16 + brow, 2*ks + bsel, 1));
                LDMX4(bl0,bl1,bl2,bl3, tadr(aKl, np*16 + brow, 2*ks + bsel, 1));
                MMA16816(oacc[2*np  ], ah0,ah1,ah2,ah3, bh0,bh1);
                MMA16816(oacc[2*np  ], ah0,ah1,ah2,ah3, bl0,bl1);
                MMA16816(oacc[2*np  ], al0,al1,al2,al3, bh0,bh1);
                MMA16816(oacc[2*np+1], ah0,ah1,ah2,ah3, bh2,bh3);
                MMA16816(oacc[2*np+1], ah0,ah1,ah2,ah3, bl2,bl3);
                MMA16816(oacc[2*np+1], al0,al1,al2,al3, bh2,bh3);
            }
        }
    }

    // ---- epilogue ----
    lsum0 += __shfl_xor_sync(0xffffffff, lsum0, 1);
    lsum0 += __shfl_xor_sync(0xffffffff, lsum0, 2);
    lsum1 += __shfl_xor_sync(0xffffffff, lsum1, 1);
    lsum1 += __shfl_xor_sync(0xffffffff, lsum1, 2);

    size_t g0 = (size_t)b*SS + i0 + warp_m + (lane >> 2);
    size_t g1 = g0 + 8;
    float mf0 = (q0g[g0] != 0.0f && k0g[g0] != 0.0f) ? (1.0f / lsum0) : 0.0f;
    float mf1 = (q0g[g1] != 0.0f && k0g[g1] != 0.0f) ? (1.0f / lsum1) : 0.0f;

    float2* O0 = reinterpret_cast<float2*>(Out + g0*DD);
    float2* O1 = reinterpret_cast<float2*>(Out + g1*DD);
    int cbase = (lane & 3);   // float2 index within each 8-col group
    #pragma unroll
    for (int nf = 0; nf < 32; nf++) {
        O0[nf*4 + cbase] = make_float2(oacc[nf][0]*mf0, oacc[nf][1]*mf0);
        O1[nf*4 + cbase] = make_float2(oacc[nf][2]*mf1, oacc[nf][3]*mf1);
    }
}

// ---------------------------------------------------------------------------
extern "C" void kernel_launch(void* const* d_in, const int* in_sizes, int n_in,
                              void* d_out, int out_size)
{
    const float* src = (const float*)d_in[0];
    const float* Wq  = (const float*)d_in[1];
    const float* bq  = (const float*)d_in[2];
    const float* Wk  = (const float*)d_in[3];
    const float* bk  = (const float*)d_in[4];
    const float* Wv  = (const float*)d_in[5];
    const float* bv  = (const float*)d_in[6];
    const float* Wo  = (const float*)d_in[7];
    const float* bo  = (const float*)d_in[8];
    float* out = (float*)d_out;

    __half *pQh, *pQl, *pKh, *pKl, *pVh, *pVl;
    float *pq0, *pk0, *pO;
    cudaGetSymbolAddress((void**)&pQh, g_Qhi);
    cudaGetSymbolAddress((void**)&pQl, g_Qlo);
    cudaGetSymbolAddress((void**)&pKh, g_Khi);
    cudaGetSymbolAddress((void**)&pKl, g_Klo);
    cudaGetSymbolAddress((void**)&pVh, g_Vthi);
    cudaGetSymbolAddress((void**)&pVl, g_Vtlo);
    cudaGetSymbolAddress((void**)&pq0, g_q0);
    cudaGetSymbolAddress((void**)&pk0, g_k0);
    cudaGetSymbolAddress((void**)&pO, g_O);

    dim3 pg(NN/64, DD/64);  // (256, 4)
    proj_qk_kernel<<<pg, 256>>>(src, Wq, bq, pQh, pQl, pq0, 0.0625f);
    proj_qk_kernel<<<pg, 256>>>(src, Wk, bk, pKh, pKl, pk0, 1.0f);
    proj_vt_kernel<<<pg, 256>>>(src, Wv, bv, pVh, pVl);

    cudaFuncSetAttribute(flash_mma, cudaFuncAttributeMaxDynamicSharedMemorySize, FL_SMEM);
    flash_mma<<<dim3(SS/128, BB), 256, FL_SMEM>>>(pQh, pQl, pKh, pKl, pVh, pVl, pq0, pk0, pO);

    proj_kernel<<<pg, 256>>>(pO, Wo, bo, out);
}

// round 5
// speedup vs baseline: 5.7781x; 3.0450x over previous
#include <cuda_runtime.h>
#include <cuda_fp16.h>
#include <cstdint>

#define BB 4
#define SS 4096
#define DD 256
#define NN (BB*SS)

// ---------------- device scratch ----------------
__device__ __half g_Qh[NN*DD];
__device__ __half g_Kh[NN*DD];
__device__ __half g_Vth[NN*DD];   // [b][d][s]
__device__ float g_q0[NN];
__device__ float g_k0[NN];
__device__ float g_O[NN*DD];

// ---------------- helpers ----------------
#define SWZ(o) ((o) ^ (((o) >> 3) & 0x70))

__device__ __forceinline__ uint32_t smem_u32(const void* p){
    uint32_t a;
    asm("{ .reg .u64 t; cvta.to.shared.u64 t, %1; cvt.u32.u64 %0, t; }" : "=r"(a) : "l"(p));
    return a;
}
__device__ __forceinline__ void sts32(uint32_t a, uint32_t v){
    asm volatile("st.shared.b32 [%0], %1;" :: "r"(a), "r"(v) : "memory");
}
__device__ __forceinline__ void cpa16(uint32_t s, const void* g){
    asm volatile("cp.async.cg.shared.global [%0], [%1], 16;" :: "r"(s), "l"(g) : "memory");
}
#define CPA_COMMIT() asm volatile("cp.async.commit_group;" ::: "memory")
#define CPA_WAIT(n)  asm volatile("cp.async.wait_group %0;" :: "n"(n) : "memory")

#define LDMX4(d0,d1,d2,d3,a) \
    asm volatile("ldmatrix.sync.aligned.m8n8.x4.shared.b16 {%0,%1,%2,%3}, [%4];" \
                 : "=r"(d0),"=r"(d1),"=r"(d2),"=r"(d3) : "r"(a))
#define MMA16816(c,a0,a1,a2,a3,b0,b1) \
    asm volatile("mma.sync.aligned.m16n8k16.row.col.f32.f16.f16.f32 " \
                 "{%0,%1,%2,%3},{%4,%5,%6,%7},{%8,%9},{%0,%1,%2,%3};" \
                 : "+f"((c)[0]),"+f"((c)[1]),"+f"((c)[2]),"+f"((c)[3]) \
                 : "r"(a0),"r"(a1),"r"(a2),"r"(a3),"r"(b0),"r"(b1))

// blocked-atom swizzled smem address of 16B chunk (r, c16); apg = atoms per 8-row group
__device__ __forceinline__ uint32_t tadr(uint32_t base, int r, int c16, int apg){
    return base + (uint32_t)(((((r>>3)*apg + (c16>>3))<<10)) +
                             SWZ((uint32_t)(((r&7)<<7) | ((c16&7)<<4))));
}

// ---------------------------------------------------------------------------
// proj_qk: C = A W^T + b -> fp16 (scaled); col0 fp32 saved for mask
// ---------------------------------------------------------------------------
__global__ __launch_bounds__(256) void proj_qk_kernel(
    const float* __restrict__ A, const float* __restrict__ W,
    const float* __restrict__ bias,
    __half* __restrict__ C16, float* __restrict__ col0, float scale)
{
    __shared__ float4 As[64*17];
    __shared__ float4 Ws[64*17];
    const int tid = threadIdx.x, ty = tid >> 4, tx = tid & 15;
    const int i0 = blockIdx.x * 64, j0 = blockIdx.y * 64;
    float acc[4][4] = {};
    const float4* A4 = reinterpret_cast<const float4*>(A) + (size_t)i0 * 64;
    const float4* W4 = reinterpret_cast<const float4*>(W) + (size_t)j0 * 64;
    for (int k0 = 0; k0 < 64; k0 += 16) {
        #pragma unroll
        for (int t = 0; t < 4; t++) {
            int idx = tid + t * 256, r = idx >> 4, e4 = idx & 15;
            As[r*17 + e4] = A4[(size_t)r*64 + k0 + e4];
            Ws[r*17 + e4] = W4[(size_t)r*64 + k0 + e4];
        }
        __syncthreads();
        #pragma unroll
        for (int e4 = 0; e4 < 16; e4++) {
            float4 a[4], w[4];
            #pragma unroll
            for (int r = 0; r < 4; r++) a[r] = As[(ty + 16*r)*17 + e4];
            #pragma unroll
            for (int c = 0; c < 4; c++) w[c] = Ws[(tx + 16*c)*17 + e4];
            #pragma unroll
            for (int r = 0; r < 4; r++)
                #pragma unroll
                for (int c = 0; c < 4; c++)
                    acc[r][c] += a[r].x*w[c].x + a[r].y*w[c].y + a[r].z*w[c].z + a[r].w*w[c].w;
        }
        __syncthreads();
    }
    #pragma unroll
    for (int r = 0; r < 4; r++) {
        int n = i0 + ty + 16*r;
        #pragma unroll
        for (int c = 0; c < 4; c++) {
            int m = j0 + tx + 16*c;
            float val = acc[r][c] + bias[m];
            if (m == 0) col0[n] = val;
            C16[(size_t)n*DD + m] = __float2half_rn(val * scale);
        }
    }
}

// ---------------------------------------------------------------------------
// proj_vt: V = A Wv^T + b -> transposed fp16 [b][d][s]
// ---------------------------------------------------------------------------
__global__ __launch_bounds__(256) void proj_vt_kernel(
    const float* __restrict__ A, const float* __restrict__ W,
    const float* __restrict__ bias, __half* __restrict__ Vt)
{
    __shared__ float4 As[64*17];
    __shared__ float4 Ws[64*17];
    const int tid = threadIdx.x, ty = tid >> 4, tx = tid & 15;
    const int i0 = blockIdx.x * 64, j0 = blockIdx.y * 64;
    float acc[4][4] = {};
    const float4* A4 = reinterpret_cast<const float4*>(A) + (size_t)i0 * 64;
    const float4* W4 = reinterpret_cast<const float4*>(W) + (size_t)j0 * 64;
    for (int k0 = 0; k0 < 64; k0 += 16) {
        #pragma unroll
        for (int t = 0; t < 4; t++) {
            int idx = tid + t * 256, r = idx >> 4, e4 = idx & 15;
            As[r*17 + e4] = A4[(size_t)r*64 + k0 + e4];
            Ws[r*17 + e4] = W4[(size_t)r*64 + k0 + e4];
        }
        __syncthreads();
        #pragma unroll
        for (int e4 = 0; e4 < 16; e4++) {
            float4 a[4], w[4];
            #pragma unroll
            for (int r = 0; r < 4; r++) a[r] = As[(ty + 16*r)*17 + e4];
            #pragma unroll
            for (int c = 0; c < 4; c++) w[c] = Ws[(tx + 16*c)*17 + e4];
            #pragma unroll
            for (int r = 0; r < 4; r++)
                #pragma unroll
                for (int c = 0; c < 4; c++)
                    acc[r][c] += a[r].x*w[c].x + a[r].y*w[c].y + a[r].z*w[c].z + a[r].w*w[c].w;
        }
        __syncthreads();
    }
    float* st = reinterpret_cast<float*>(As);   // [s_local][d_local] 64x65
    #pragma unroll
    for (int r = 0; r < 4; r++)
        #pragma unroll
        for (int c = 0; c < 4; c++)
            st[(ty + 16*r)*65 + (tx + 16*c)] = acc[r][c] + bias[j0 + tx + 16*c];
    __syncthreads();

    const int b = i0 >> 12, s0 = i0 & 4095;
    uint4* V4 = reinterpret_cast<uint4*>(Vt);
    #pragma unroll
    for (int t = 0; t < 2; t++) {
        int idx = tid + t * 256;           // 0..511
        int dl = idx >> 3, ch = idx & 7;
        uint32_t hh[4];
        #pragma unroll
        for (int e2 = 0; e2 < 4; e2++) {
            __half2 h2 = __floats2half2_rn(st[(ch*8 + 2*e2)*65 + dl],
                                           st[(ch*8 + 2*e2 + 1)*65 + dl]);
            hh[e2] = *reinterpret_cast<uint32_t*>(&h2);
        }
        size_t oidx = ((size_t)b*DD + j0 + dl)*512 + (s0 >> 3) + ch;
        V4[oidx] = make_uint4(hh[0], hh[1], hh[2], hh[3]);
    }
}

// ---------------------------------------------------------------------------
// proj (fp32 out) — final Wo projection
// ---------------------------------------------------------------------------
__global__ __launch_bounds__(256) void proj_kernel(
    const float* __restrict__ A, const float* __restrict__ W,
    const float* __restrict__ bias, float* __restrict__ C)
{
    __shared__ float4 As[64*17];
    __shared__ float4 Ws[64*17];
    const int tid = threadIdx.x, ty = tid >> 4, tx = tid & 15;
    const int i0 = blockIdx.x * 64, j0 = blockIdx.y * 64;
    float acc[4][4] = {};
    const float4* A4 = reinterpret_cast<const float4*>(A) + (size_t)i0 * 64;
    const float4* W4 = reinterpret_cast<const float4*>(W) + (size_t)j0 * 64;
    for (int k0 = 0; k0 < 64; k0 += 16) {
        #pragma unroll
        for (int t = 0; t < 4; t++) {
            int idx = tid + t * 256, r = idx >> 4, e4 = idx & 15;
            As[r*17 + e4] = A4[(size_t)r*64 + k0 + e4];
            Ws[r*17 + e4] = W4[(size_t)r*64 + k0 + e4];
        }
        __syncthreads();
        #pragma unroll
        for (int e4 = 0; e4 < 16; e4++) {
            float4 a[4], w[4];
            #pragma unroll
            for (int r = 0; r < 4; r++) a[r] = As[(ty + 16*r)*17 + e4];
            #pragma unroll
            for (int c = 0; c < 4; c++) w[c] = Ws[(tx + 16*c)*17 + e4];
            #pragma unroll
            for (int r = 0; r < 4; r++)
                #pragma unroll
                for (int c = 0; c < 4; c++)
                    acc[r][c] += a[r].x*w[c].x + a[r].y*w[c].y + a[r].z*w[c].z + a[r].w*w[c].w;
        }
        __syncthreads();
    }
    #pragma unroll
    for (int r = 0; r < 4; r++) {
        int n = i0 + ty + 16*r;
        #pragma unroll
        for (int c = 0; c < 4; c++)
            C[(size_t)n*DD + j0 + tx + 16*c] = acc[r][c] + bias[j0 + tx + 16*c];
    }
}

// ---------------------------------------------------------------------------
// flash_mma: single-fp16 mma.sync flash attention, cp.async double-buffered.
// 128 queries/CTA, 8 warps as 4M x 2N grid (32-row strips; 32/128-col halves).
// SMEM: Q 64K | K ping-pong 2x32K | V ping-pong 2x32K | P 16K = 208K
// ---------------------------------------------------------------------------
#define OFF_Q    0u
#define OFF_K0   65536u
#define OFF_K1   98304u
#define OFF_V0   131072u
#define OFF_V1   163840u
#define OFF_P    196608u
#define FL_SMEM  (212992 + 1024)

__global__ __launch_bounds__(256, 1) void flash_mma(
    const __half* __restrict__ Qh_, const __half* __restrict__ Kh_,
    const __half* __restrict__ Vth_,
    const float* __restrict__ q0g, const float* __restrict__ k0g,
    float* __restrict__ Out)
{
    extern __shared__ char fsm[];
    const uint32_t raw = smem_u32(fsm);
    const uint32_t abase = (raw + 1023u) & ~1023u;
    char* cbase = fsm + (abase - raw);
    const uint32_t aQ = abase + OFF_Q;
    const uint32_t aK[2] = { abase + OFF_K0, abase + OFF_K1 };
    const uint32_t aV[2] = { abase + OFF_V0, abase + OFF_V1 };
    const uint32_t aP = abase + OFF_P;

    const int tid = threadIdx.x, wid = tid >> 5, lane = tid & 31;
    const int mi = wid >> 1, ni = wid & 1;
    const int b = blockIdx.y, i0 = blockIdx.x * 128;

    // ldmatrix lane addressing
    const int mat = lane >> 3, lr = lane & 7;
    const int arow = (mat & 1) * 8 + lr;
    const int asel = mat >> 1;
    const int brow = ((mat >> 1) << 3) + lr;
    const int bsel = mat & 1;

    const uint4* Qg4 = reinterpret_cast<const uint4*>(Qh_) + ((size_t)(b*SS + i0)) * 32;
    const uint4* Kg4 = reinterpret_cast<const uint4*>(Kh_) + (size_t)b*SS*32;
    const uint4* Vg4 = reinterpret_cast<const uint4*>(Vth_) + (size_t)b*DD*512;

    // ---- prologue: async load Q, K(0), V(0) ----
    #pragma unroll
    for (int t = 0; t < 16; t++) {
        int idx = tid + t * 256;          // 0..4095
        int r = idx >> 5, c = idx & 31;
        cpa16(tadr(aQ, r, c, 4), Qg4 + (size_t)r*32 + c);
    }
    CPA_COMMIT();
    #pragma unroll
    for (int t = 0; t < 8; t++) {
        int idx = tid + t * 256;
        int r = idx >> 5, c = idx & 31;
        cpa16(tadr(aK[0], r, c, 4), Kg4 + (size_t)r*32 + c);
    }
    CPA_COMMIT();
    #pragma unroll
    for (int t = 0; t < 8; t++) {
        int idx = tid + t * 256;
        int r = idx >> 3, c = idx & 7;
        cpa16(tadr(aV[0], r, c, 1), Vg4 + (size_t)r*512 + c);
    }
    CPA_COMMIT();

    float oacc[2][16][4];
    #pragma unroll
    for (int m2 = 0; m2 < 2; m2++)
        #pragma unroll
        for (int nf = 0; nf < 16; nf++)
            #pragma unroll
            for (int j = 0; j < 4; j++) oacc[m2][nf][j] = 0.0f;
    float lsum[2][2] = {{0.f,0.f},{0.f,0.f}};

    for (int kt = 0; kt < SS/64; kt++) {
        const int buf = kt & 1;
        __syncthreads();                 // MMA2(kt-1) done with V/P; MMA1(kt-1) long done
        if (kt + 1 < SS/64) {
            const int nb = buf ^ 1;
            #pragma unroll
            for (int t = 0; t < 8; t++) {
                int idx = tid + t * 256;
                int r = idx >> 5, c = idx & 31;
                cpa16(tadr(aK[nb], r, c, 4), Kg4 + (size_t)((kt+1)*64 + r)*32 + c);
            }
            CPA_COMMIT();
            #pragma unroll
            for (int t = 0; t < 8; t++) {
                int idx = tid + t * 256;
                int r = idx >> 3, c = idx & 7;
                cpa16(tadr(aV[nb], r, c, 1), Vg4 + (size_t)r*512 + (kt+1)*8 + c);
            }
            CPA_COMMIT();
            CPA_WAIT(2);                 // K(kt), V(kt), Q complete
        } else {
            CPA_WAIT(0);
        }
        __syncthreads();

        // ---- MMA1: S = Q K^T  (warp tile 32 x 32) ----
        float sacc[2][4][4];
        #pragma unroll
        for (int m2 = 0; m2 < 2; m2++)
            #pragma unroll
            for (int nf = 0; nf < 4; nf++)
                #pragma unroll
                for (int j = 0; j < 4; j++) sacc[m2][nf][j] = 0.0f;

        #pragma unroll 4
        for (int ks = 0; ks < 16; ks++) {
            uint32_t a[2][4];
            #pragma unroll
            for (int m2 = 0; m2 < 2; m2++)
                LDMX4(a[m2][0],a[m2][1],a[m2][2],a[m2][3],
                      tadr(aQ, mi*32 + m2*16 + arow, 2*ks + asel, 4));
            #pragma unroll
            for (int n16 = 0; n16 < 2; n16++) {
                uint32_t b0,b1,b2,b3;
                LDMX4(b0,b1,b2,b3,
                      tadr(aK[buf], ni*32 + n16*16 + brow, 2*ks + bsel, 4));
                #pragma unroll
                for (int m2 = 0; m2 < 2; m2++) {
                    MMA16816(sacc[m2][n16*2  ], a[m2][0],a[m2][1],a[m2][2],a[m2][3], b0,b1);
                    MMA16816(sacc[m2][n16*2+1], a[m2][0],a[m2][1],a[m2][2],a[m2][3], b2,b3);
                }
            }
        }

        // ---- softmax (no max-sub) -> P fp16 to smem ----
        {
            const int r0 = lane >> 2;
            const int ib = (lane & 3) * 4;
            #pragma unroll
            for (int m2 = 0; m2 < 2; m2++) {
                #pragma unroll
                for (int nf = 0; nf < 4; nf++) {
                    float e0 = __expf(sacc[m2][nf][0]);
                    float e1 = __expf(sacc[m2][nf][1]);
                    float e2 = __expf(sacc[m2][nf][2]);
                    float e3 = __expf(sacc[m2][nf][3]);
                    lsum[m2][0] += e0 + e1;
                    lsum[m2][1] += e2 + e3;
                    __half2 h01 = __floats2half2_rn(e0, e1);
                    __half2 h23 = __floats2half2_rn(e2, e3);
                    int row = mi*32 + m2*16 + r0;
                    sts32(tadr(aP, row,     ni*4 + nf, 1) + ib,
                          *reinterpret_cast<uint32_t*>(&h01));
                    sts32(tadr(aP, row + 8, ni*4 + nf, 1) + ib,
                          *reinterpret_cast<uint32_t*>(&h23));
                }
            }
        }
        __syncthreads();                 // P visible to all warps

        // ---- MMA2: O += P V  (warp tile 32 x 128) ----
        #pragma unroll
        for (int ks = 0; ks < 4; ks++) {
            uint32_t a[2][4];
            #pragma unroll
            for (int m2 = 0; m2 < 2; m2++)
                LDMX4(a[m2][0],a[m2][1],a[m2][2],a[m2][3],
                      tadr(aP, mi*32 + m2*16 + arow, 2*ks + asel, 1));
            #pragma unroll
            for (int n16 = 0; n16 < 8; n16++) {
                uint32_t b0,b1,b2,b3;
                LDMX4(b0,b1,b2,b3,
                      tadr(aV[buf], ni*128 + n16*16 + brow, 2*ks + bsel, 1));
                #pragma unroll
                for (int m2 = 0; m2 < 2; m2++) {
                    MMA16816(oacc[m2][n16*2  ], a[m2][0],a[m2][1],a[m2][2],a[m2][3], b0,b1);
                    MMA16816(oacc[m2][n16*2+1], a[m2][0],a[m2][1],a[m2][2],a[m2][3], b2,b3);
                }
            }
        }
    }

    // ---- epilogue: cross-warp lsum combine, mask, normalize, store ----
    __syncthreads();
    float* Lsh = reinterpret_cast<float*>(cbase + OFF_P);   // reuse P region
    {
        const int r0 = lane >> 2;
        #pragma unroll
        for (int m2 = 0; m2 < 2; m2++)
            #pragma unroll
            for (int h = 0; h < 2; h++) {
                float v = lsum[m2][h];
                v += __shfl_xor_sync(0xffffffff, v, 1);
                v += __shfl_xor_sync(0xffffffff, v, 2);
                if ((lane & 3) == 0)
                    Lsh[(mi*32 + m2*16 + h*8 + r0)*2 + ni] = v;
            }
    }
    __syncthreads();
    {
        const int r0 = lane >> 2;
        #pragma unroll
        for (int m2 = 0; m2 < 2; m2++) {
            int row0 = mi*32 + m2*16 + r0;
            size_t g0 = (size_t)b*SS + i0 + row0;
            size_t g1 = g0 + 8;
            float l0 = Lsh[row0*2] + Lsh[row0*2 + 1];
            float l1 = Lsh[(row0+8)*2] + Lsh[(row0+8)*2 + 1];
            float mf0 = (q0g[g0] != 0.0f && k0g[g0] != 0.0f) ? (1.0f / l0) : 0.0f;
            float mf1 = (q0g[g1] != 0.0f && k0g[g1] != 0.0f) ? (1.0f / l1) : 0.0f;
            float2* O0 = reinterpret_cast<float2*>(Out + g0*DD);
            float2* O1 = reinterpret_cast<float2*>(Out + g1*DD);
            int cb = lane & 3;
            #pragma unroll
            for (int nf = 0; nf < 16; nf++) {
                int f2 = ni*64 + nf*4 + cb;
                O0[f2] = make_float2(oacc[m2][nf][0]*mf0, oacc[m2][nf][1]*mf0);
                O1[f2] = make_float2(oacc[m2][nf][2]*mf1, oacc[m2][nf][3]*mf1);
            }
        }
    }
}

// ---------------------------------------------------------------------------
extern "C" void kernel_launch(void* const* d_in, const int* in_sizes, int n_in,
                              void* d_out, int out_size)
{
    const float* src = (const float*)d_in[0];
    const float* Wq  = (const float*)d_in[1];
    const float* bq  = (const float*)d_in[2];
    const float* Wk  = (const float*)d_in[3];
    const float* bk  = (const float*)d_in[4];
    const float* Wv  = (const float*)d_in[5];
    const float* bv  = (const float*)d_in[6];
    const float* Wo  = (const float*)d_in[7];
    const float* bo  = (const float*)d_in[8];
    float* out = (float*)d_out;

    __half *pQ, *pK, *pV;
    float *pq0, *pk0, *pO;
    cudaGetSymbolAddress((void**)&pQ, g_Qh);
    cudaGetSymbolAddress((void**)&pK, g_Kh);
    cudaGetSymbolAddress((void**)&pV, g_Vth);
    cudaGetSymbolAddress((void**)&pq0, g_q0);
    cudaGetSymbolAddress((void**)&pk0, g_k0);
    cudaGetSymbolAddress((void**)&pO, g_O);

    dim3 pg(NN/64, DD/64);  // (256, 4)
    proj_qk_kernel<<<pg, 256>>>(src, Wq, bq, pQ, pq0, 0.0625f);
    proj_qk_kernel<<<pg, 256>>>(src, Wk, bk, pK, pk0, 1.0f);
    proj_vt_kernel<<<pg, 256>>>(src, Wv, bv, pV);

    cudaFuncSetAttribute(flash_mma, cudaFuncAttributeMaxDynamicSharedMemorySize, FL_SMEM);
    flash_mma<<<dim3(SS/128, BB), 256, FL_SMEM>>>(pQ, pK, pV, pq0, pk0, pO);

    proj_kernel<<<pg, 256>>>(pO, Wo, bo, out);
}

// round 6
// speedup vs baseline: 8.4378x; 1.4603x over previous
#include <cuda_runtime.h>
#include <cuda_fp16.h>
#include <cstdint>

#define BB 4
#define SS 4096
#define DD 256
#define NN (BB*SS)

// ---------------- device scratch ----------------
__device__ __half g_srcHi[NN*DD];
__device__ __half g_srcLo[NN*DD];
__device__ __half g_WqHi[DD*DD];
__device__ __half g_WqLo[DD*DD];
__device__ __half g_WkHi[DD*DD];
__device__ __half g_WkLo[DD*DD];
__device__ __half g_WvHi[DD*DD];
__device__ __half g_WvLo[DD*DD];
__device__ __half g_WoHi[DD*DD];
__device__ __half g_WoLo[DD*DD];
__device__ __half g_Qh[NN*DD];
__device__ __half g_Kh[NN*DD];
__device__ __half g_Vth[NN*DD];   // [b][d][s]
__device__ __half g_Ohi[NN*DD];
__device__ __half g_Olo[NN*DD];
__device__ float g_q0[NN];
__device__ float g_k0[NN];

// ---------------- helpers ----------------
#define SWZ(o) ((o) ^ (((o) >> 3) & 0x70))

__device__ __forceinline__ uint32_t smem_u32(const void* p){
    uint32_t a;
    asm("{ .reg .u64 t; cvta.to.shared.u64 t, %1; cvt.u32.u64 %0, t; }" : "=r"(a) : "l"(p));
    return a;
}
__device__ __forceinline__ void sts32(uint32_t a, uint32_t v){
    asm volatile("st.shared.b32 [%0], %1;" :: "r"(a), "r"(v) : "memory");
}
__device__ __forceinline__ void cpa16(uint32_t s, const void* g){
    asm volatile("cp.async.cg.shared.global [%0], [%1], 16;" :: "r"(s), "l"(g) : "memory");
}
#define CPA_COMMIT() asm volatile("cp.async.commit_group;" ::: "memory")
#define CPA_WAIT(n)  asm volatile("cp.async.wait_group %0;" :: "n"(n) : "memory")

#define LDMX4(d0,d1,d2,d3,a) \
    asm volatile("ldmatrix.sync.aligned.m8n8.x4.shared.b16 {%0,%1,%2,%3}, [%4];" \
                 : "=r"(d0),"=r"(d1),"=r"(d2),"=r"(d3) : "r"(a))
#define MMA16816(c,a0,a1,a2,a3,b0,b1) \
    asm volatile("mma.sync.aligned.m16n8k16.row.col.f32.f16.f16.f32 " \
                 "{%0,%1,%2,%3},{%4,%5,%6,%7},{%8,%9},{%0,%1,%2,%3};" \
                 : "+f"((c)[0]),"+f"((c)[1]),"+f"((c)[2]),"+f"((c)[3]) \
                 : "r"(a0),"r"(a1),"r"(a2),"r"(a3),"r"(b0),"r"(b1))

// blocked-atom swizzled smem address of 16B chunk (r, c16); apg = atoms per 8-row group
__device__ __forceinline__ uint32_t tadr(uint32_t base, int r, int c16, int apg){
    return base + (uint32_t)(((((r>>3)*apg + (c16>>3))<<10)) +
                             SWZ((uint32_t)(((r&7)<<7) | ((c16&7)<<4))));
}
__device__ __forceinline__ void hsplit(float x, __half& h, __half& l){
    h = __float2half_rn(x);
    l = __float2half_rn(x - __half2float(h));
}

// ---------------------------------------------------------------------------
// split_kernel: fp32 -> fp16 hi/lo, float4 granularity
// ---------------------------------------------------------------------------
__global__ __launch_bounds__(256) void split_kernel(
    const float4* __restrict__ in, uint2* __restrict__ hi,
    uint2* __restrict__ lo, int n4)
{
    int i = blockIdx.x * 256 + threadIdx.x;
    if (i >= n4) return;
    float4 v = in[i];
    __half hx,lx,hy,ly,hz,lz,hw,lw;
    hsplit(v.x,hx,lx); hsplit(v.y,hy,ly); hsplit(v.z,hz,lz); hsplit(v.w,hw,lw);
    __half2 h01 = __halves2half2(hx,hy), h23 = __halves2half2(hz,hw);
    __half2 l01 = __halves2half2(lx,ly), l23 = __halves2half2(lz,lw);
    hi[i] = make_uint2(*reinterpret_cast<uint32_t*>(&h01), *reinterpret_cast<uint32_t*>(&h23));
    lo[i] = make_uint2(*reinterpret_cast<uint32_t*>(&l01), *reinterpret_cast<uint32_t*>(&l23));
}

// ---------------------------------------------------------------------------
// proj_mma: C = A W^T + bias, split fp16 x3 MMA, fp32 accumulate.
// CTA 128x128, 8 warps (4M x 2N), K chunks of 64 double-buffered.
// mode 0: outH fp16 (val*scale) row-major + col0 fp32
// mode 2: outH fp16 transposed [b][d][s]
// mode 3: outF fp32 row-major
// ---------------------------------------------------------------------------
#define PJ_SMEM (131072 + 1024)

__global__ __launch_bounds__(256, 1) void proj_mma(
    const __half* __restrict__ Ahi_, const __half* __restrict__ Alo_,
    const __half* __restrict__ Whi_, const __half* __restrict__ Wlo_,
    const float* __restrict__ bias,
    __half* __restrict__ outH, float* __restrict__ outF,
    float* __restrict__ col0, int mode, float scale)
{
    extern __shared__ char psm[];
    const uint32_t raw = smem_u32(psm);
    const uint32_t abase = (raw + 1023u) & ~1023u;
    char* cbase = psm + (abase - raw);

    const int tid = threadIdx.x, wid = tid >> 5, lane = tid & 31;
    const int mi = wid >> 1, ni = wid & 1;
    const int i0 = blockIdx.x * 128, j0 = blockIdx.y * 128;

    const int mat = lane >> 3, lr = lane & 7;
    const int arow = (mat & 1) * 8 + lr;
    const int asel = mat >> 1;
    const int brow = ((mat >> 1) << 3) + lr;
    const int bsel = mat & 1;

    const uint4* Ah4 = reinterpret_cast<const uint4*>(Ahi_);
    const uint4* Al4 = reinterpret_cast<const uint4*>(Alo_);
    const uint4* Wh4 = reinterpret_cast<const uint4*>(Whi_);
    const uint4* Wl4 = reinterpret_cast<const uint4*>(Wlo_);

    // buffer b at abase + b*65536: Ah@0 Al@16K Wh@32K Wl@48K
    auto loadChunk = [&](int kc, int b){
        const uint32_t bb = abase + (uint32_t)b * 65536u;
        #pragma unroll
        for (int t = 0; t < 4; t++) {
            int idx = tid + t * 256;      // 0..1023
            int r = idx >> 3, c = idx & 7;
            size_t ga = (size_t)(i0 + r) * 32 + kc * 8 + c;
            size_t gw = (size_t)(j0 + r) * 32 + kc * 8 + c;
            cpa16(tadr(bb,          r, c, 1), Ah4 + ga);
            cpa16(tadr(bb + 16384u, r, c, 1), Al4 + ga);
            cpa16(tadr(bb + 32768u, r, c, 1), Wh4 + gw);
            cpa16(tadr(bb + 49152u, r, c, 1), Wl4 + gw);
        }
        CPA_COMMIT();
    };

    float oacc[2][8][4];
    #pragma unroll
    for (int m2 = 0; m2 < 2; m2++)
        #pragma unroll
        for (int nf = 0; nf < 8; nf++)
            #pragma unroll
            for (int j = 0; j < 4; j++) oacc[m2][nf][j] = 0.0f;

    loadChunk(0, 0);
    for (int kc = 0; kc < 4; kc++) {
        __syncthreads();                  // prev MMA done reading target buffer
        if (kc < 3) { loadChunk(kc + 1, (kc + 1) & 1); CPA_WAIT(1); }
        else        { CPA_WAIT(0); }
        __syncthreads();

        const uint32_t bb = abase + (uint32_t)(kc & 1) * 65536u;
        const uint32_t bAh = bb, bAl = bb + 16384u, bWh = bb + 32768u, bWl = bb + 49152u;
        #pragma unroll
        for (int ks = 0; ks < 4; ks++) {
            uint32_t ah[2][4], al[2][4];
            #pragma unroll
            for (int m2 = 0; m2 < 2; m2++) {
                LDMX4(ah[m2][0],ah[m2][1],ah[m2][2],ah[m2][3],
                      tadr(bAh, mi*32 + m2*16 + arow, 2*ks + asel, 1));
                LDMX4(al[m2][0],al[m2][1],al[m2][2],al[m2][3],
                      tadr(bAl, mi*32 + m2*16 + arow, 2*ks + asel, 1));
            }
            #pragma unroll
            for (int n16 = 0; n16 < 4; n16++) {
                uint32_t bh0,bh1,bh2,bh3, bl0,bl1,bl2,bl3;
                LDMX4(bh0,bh1,bh2,bh3, tadr(bWh, ni*64 + n16*16 + brow, 2*ks + bsel, 1));
                LDMX4(bl0,bl1,bl2,bl3, tadr(bWl, ni*64 + n16*16 + brow, 2*ks + bsel, 1));
                #pragma unroll
                for (int m2 = 0; m2 < 2; m2++) {
                    MMA16816(oacc[m2][n16*2  ], ah[m2][0],ah[m2][1],ah[m2][2],ah[m2][3], bh0,bh1);
                    MMA16816(oacc[m2][n16*2  ], ah[m2][0],ah[m2][1],ah[m2][2],ah[m2][3], bl0,bl1);
                    MMA16816(oacc[m2][n16*2  ], al[m2][0],al[m2][1],al[m2][2],al[m2][3], bh0,bh1);
                    MMA16816(oacc[m2][n16*2+1], ah[m2][0],ah[m2][1],ah[m2][2],ah[m2][3], bh2,bh3);
                    MMA16816(oacc[m2][n16*2+1], ah[m2][0],ah[m2][1],ah[m2][2],ah[m2][3], bl2,bl3);
                    MMA16816(oacc[m2][n16*2+1], al[m2][0],al[m2][1],al[m2][2],al[m2][3], bh2,bh3);
                }
            }
        }
    }

    const int r0 = lane >> 2, cb = lane & 3;

    if (mode == 2) {
        // stage fp32 tile [row][col] stride 129, then transposed coalesced write
        __syncthreads();
        float* st = reinterpret_cast<float*>(cbase);
        #pragma unroll
        for (int m2 = 0; m2 < 2; m2++)
            #pragma unroll
            for (int nf = 0; nf < 8; nf++) {
                int r = mi*32 + m2*16 + r0;
                int c = ni*64 + nf*8 + cb*2;
                float b0v = bias[j0 + c], b1v = bias[j0 + c + 1];
                st[r*129 + c]       = oacc[m2][nf][0] + b0v;
                st[r*129 + c + 1]   = oacc[m2][nf][1] + b1v;
                st[(r+8)*129 + c]   = oacc[m2][nf][2] + b0v;
                st[(r+8)*129 + c+1] = oacc[m2][nf][3] + b1v;
            }
        __syncthreads();
        const int b = i0 >> 12, s0 = i0 & 4095;
        uint4* V4 = reinterpret_cast<uint4*>(outH);
        #pragma unroll
        for (int t = 0; t < 8; t++) {
            int idx = tid + t * 256;      // 0..2047
            int dl = idx >> 4, sc = idx & 15;
            uint32_t hh[4];
            #pragma unroll
            for (int e = 0; e < 4; e++) {
                __half2 h2 = __floats2half2_rn(st[(sc*8 + 2*e)*129 + dl],
                                               st[(sc*8 + 2*e + 1)*129 + dl]);
                hh[e] = *reinterpret_cast<uint32_t*>(&h2);
            }
            V4[((size_t)(b*DD + j0 + dl))*512 + (s0 >> 3) + sc] =
                make_uint4(hh[0], hh[1], hh[2], hh[3]);
        }
        return;
    }

    #pragma unroll
    for (int m2 = 0; m2 < 2; m2++)
        #pragma unroll
        for (int nf = 0; nf < 8; nf++) {
            int r = mi*32 + m2*16 + r0;
            int c = ni*64 + nf*8 + cb*2;
            float b0v = bias[j0 + c], b1v = bias[j0 + c + 1];
            float v00 = oacc[m2][nf][0] + b0v, v01 = oacc[m2][nf][1] + b1v;
            float v10 = oacc[m2][nf][2] + b0v, v11 = oacc[m2][nf][3] + b1v;
            size_t n0 = (size_t)(i0 + r), n1 = n0 + 8;
            if (mode == 0) {
                if (col0 && j0 + c == 0) { col0[n0] = v00; col0[n1] = v10; }
                __half2 a2 = __floats2half2_rn(v00*scale, v01*scale);
                __half2 c2 = __floats2half2_rn(v10*scale, v11*scale);
                reinterpret_cast<uint32_t*>(outH)[(n0*DD + j0 + c) >> 1] =
                    *reinterpret_cast<uint32_t*>(&a2);
                reinterpret_cast<uint32_t*>(outH)[(n1*DD + j0 + c) >> 1] =
                    *reinterpret_cast<uint32_t*>(&c2);
            } else {   // mode 3
                reinterpret_cast<float2*>(outF)[(n0*DD + j0 + c) >> 1] = make_float2(v00, v01);
                reinterpret_cast<float2*>(outF)[(n1*DD + j0 + c) >> 1] = make_float2(v10, v11);
            }
        }
}

// ---------------------------------------------------------------------------
// flash_mma: single-fp16 mma.sync flash attention, cp.async double-buffered.
// Writes O as fp16 hi/lo for the final projection.
// ---------------------------------------------------------------------------
#define OFF_Q    0u
#define OFF_K0   65536u
#define OFF_K1   98304u
#define OFF_V0   131072u
#define OFF_V1   163840u
#define OFF_P    196608u
#define FL_SMEM  (212992 + 1024)

__global__ __launch_bounds__(256, 1) void flash_mma(
    const __half* __restrict__ Qh_, const __half* __restrict__ Kh_,
    const __half* __restrict__ Vth_,
    const float* __restrict__ q0g, const float* __restrict__ k0g,
    __half* __restrict__ Ohi, __half* __restrict__ Olo)
{
    extern __shared__ char fsm[];
    const uint32_t raw = smem_u32(fsm);
    const uint32_t abase = (raw + 1023u) & ~1023u;
    char* cbase = fsm + (abase - raw);
    const uint32_t aQ = abase + OFF_Q;
    const uint32_t aK[2] = { abase + OFF_K0, abase + OFF_K1 };
    const uint32_t aV[2] = { abase + OFF_V0, abase + OFF_V1 };
    const uint32_t aP = abase + OFF_P;

    const int tid = threadIdx.x, wid = tid >> 5, lane = tid & 31;
    const int mi = wid >> 1, ni = wid & 1;
    const int b = blockIdx.y, i0 = blockIdx.x * 128;

    const int mat = lane >> 3, lr = lane & 7;
    const int arow = (mat & 1) * 8 + lr;
    const int asel = mat >> 1;
    const int brow = ((mat >> 1) << 3) + lr;
    const int bsel = mat & 1;

    const uint4* Qg4 = reinterpret_cast<const uint4*>(Qh_) + ((size_t)(b*SS + i0)) * 32;
    const uint4* Kg4 = reinterpret_cast<const uint4*>(Kh_) + (size_t)b*SS*32;
    const uint4* Vg4 = reinterpret_cast<const uint4*>(Vth_) + (size_t)b*DD*512;

    #pragma unroll
    for (int t = 0; t < 16; t++) {
        int idx = tid + t * 256;
        int r = idx >> 5, c = idx & 31;
        cpa16(tadr(aQ, r, c, 4), Qg4 + (size_t)r*32 + c);
    }
    CPA_COMMIT();
    #pragma unroll
    for (int t = 0; t < 8; t++) {
        int idx = tid + t * 256;
        int r = idx >> 5, c = idx & 31;
        cpa16(tadr(aK[0], r, c, 4), Kg4 + (size_t)r*32 + c);
    }
    CPA_COMMIT();
    #pragma unroll
    for (int t = 0; t < 8; t++) {
        int idx = tid + t * 256;
        int r = idx >> 3, c = idx & 7;
        cpa16(tadr(aV[0], r, c, 1), Vg4 + (size_t)r*512 + c);
    }
    CPA_COMMIT();

    float oacc[2][16][4];
    #pragma unroll
    for (int m2 = 0; m2 < 2; m2++)
        #pragma unroll
        for (int nf = 0; nf < 16; nf++)
            #pragma unroll
            for (int j = 0; j < 4; j++) oacc[m2][nf][j] = 0.0f;
    float lsum[2][2] = {{0.f,0.f},{0.f,0.f}};

    for (int kt = 0; kt < SS/64; kt++) {
        const int buf = kt & 1;
        __syncthreads();
        if (kt + 1 < SS/64) {
            const int nb = buf ^ 1;
            #pragma unroll
            for (int t = 0; t < 8; t++) {
                int idx = tid + t * 256;
                int r = idx >> 5, c = idx & 31;
                cpa16(tadr(aK[nb], r, c, 4), Kg4 + (size_t)((kt+1)*64 + r)*32 + c);
            }
            CPA_COMMIT();
            #pragma unroll
            for (int t = 0; t < 8; t++) {
                int idx = tid + t * 256;
                int r = idx >> 3, c = idx & 7;
                cpa16(tadr(aV[nb], r, c, 1), Vg4 + (size_t)r*512 + (kt+1)*8 + c);
            }
            CPA_COMMIT();
            CPA_WAIT(2);
        } else {
            CPA_WAIT(0);
        }
        __syncthreads();

        // ---- MMA1: S = Q K^T (warp tile 32x32) ----
        float sacc[2][4][4];
        #pragma unroll
        for (int m2 = 0; m2 < 2; m2++)
            #pragma unroll
            for (int nf = 0; nf < 4; nf++)
                #pragma unroll
                for (int j = 0; j < 4; j++) sacc[m2][nf][j] = 0.0f;

        #pragma unroll 4
        for (int ks = 0; ks < 16; ks++) {
            uint32_t a[2][4];
            #pragma unroll
            for (int m2 = 0; m2 < 2; m2++)
                LDMX4(a[m2][0],a[m2][1],a[m2][2],a[m2][3],
                      tadr(aQ, mi*32 + m2*16 + arow, 2*ks + asel, 4));
            #pragma unroll
            for (int n16 = 0; n16 < 2; n16++) {
                uint32_t b0,b1,b2,b3;
                LDMX4(b0,b1,b2,b3,
                      tadr(aK[buf], ni*32 + n16*16 + brow, 2*ks + bsel, 4));
                #pragma unroll
                for (int m2 = 0; m2 < 2; m2++) {
                    MMA16816(sacc[m2][n16*2  ], a[m2][0],a[m2][1],a[m2][2],a[m2][3], b0,b1);
                    MMA16816(sacc[m2][n16*2+1], a[m2][0],a[m2][1],a[m2][2],a[m2][3], b2,b3);
                }
            }
        }

        // ---- softmax (no max-sub) -> P fp16 ----
        {
            const int r0 = lane >> 2;
            const int ib = (lane & 3) * 4;
            #pragma unroll
            for (int m2 = 0; m2 < 2; m2++) {
                #pragma unroll
                for (int nf = 0; nf < 4; nf++) {
                    float e0 = __expf(sacc[m2][nf][0]);
                    float e1 = __expf(sacc[m2][nf][1]);
                    float e2 = __expf(sacc[m2][nf][2]);
                    float e3 = __expf(sacc[m2][nf][3]);
                    lsum[m2][0] += e0 + e1;
                    lsum[m2][1] += e2 + e3;
                    __half2 h01 = __floats2half2_rn(e0, e1);
                    __half2 h23 = __floats2half2_rn(e2, e3);
                    int row = mi*32 + m2*16 + r0;
                    sts32(tadr(aP, row,     ni*4 + nf, 1) + ib,
                          *reinterpret_cast<uint32_t*>(&h01));
                    sts32(tadr(aP, row + 8, ni*4 + nf, 1) + ib,
                          *reinterpret_cast<uint32_t*>(&h23));
                }
            }
        }
        __syncthreads();

        // ---- MMA2: O += P V (warp tile 32x128) ----
        #pragma unroll
        for (int ks = 0; ks < 4; ks++) {
            uint32_t a[2][4];
            #pragma unroll
            for (int m2 = 0; m2 < 2; m2++)
                LDMX4(a[m2][0],a[m2][1],a[m2][2],a[m2][3],
                      tadr(aP, mi*32 + m2*16 + arow, 2*ks + asel, 1));
            #pragma unroll
            for (int n16 = 0; n16 < 8; n16++) {
                uint32_t b0,b1,b2,b3;
                LDMX4(b0,b1,b2,b3,
                      tadr(aV[buf], ni*128 + n16*16 + brow, 2*ks + bsel, 1));
                #pragma unroll
                for (int m2 = 0; m2 < 2; m2++) {
                    MMA16816(oacc[m2][n16*2  ], a[m2][0],a[m2][1],a[m2][2],a[m2][3], b0,b1);
                    MMA16816(oacc[m2][n16*2+1], a[m2][0],a[m2][1],a[m2][2],a[m2][3], b2,b3);
                }
            }
        }
    }

    // ---- epilogue ----
    __syncthreads();
    float* Lsh = reinterpret_cast<float*>(cbase + OFF_P);
    {
        const int r0 = lane >> 2;
        #pragma unroll
        for (int m2 = 0; m2 < 2; m2++)
            #pragma unroll
            for (int h = 0; h < 2; h++) {
                float v = lsum[m2][h];
                v += __shfl_xor_sync(0xffffffff, v, 1);
                v += __shfl_xor_sync(0xffffffff, v, 2);
                if ((lane & 3) == 0)
                    Lsh[(mi*32 + m2*16 + h*8 + r0)*2 + ni] = v;
            }
    }
    __syncthreads();
    {
        const int r0 = lane >> 2;
        #pragma unroll
        for (int m2 = 0; m2 < 2; m2++) {
            int row0 = mi*32 + m2*16 + r0;
            size_t g0 = (size_t)b*SS + i0 + row0;
            size_t g1 = g0 + 8;
            float l0 = Lsh[row0*2] + Lsh[row0*2 + 1];
            float l1 = Lsh[(row0+8)*2] + Lsh[(row0+8)*2 + 1];
            float mf0 = (q0g[g0] != 0.0f && k0g[g0] != 0.0f) ? (1.0f / l0) : 0.0f;
            float mf1 = (q0g[g1] != 0.0f && k0g[g1] != 0.0f) ? (1.0f / l1) : 0.0f;
            uint32_t* H0 = reinterpret_cast<uint32_t*>(Ohi + g0*DD);
            uint32_t* H1 = reinterpret_cast<uint32_t*>(Ohi + g1*DD);
            uint32_t* L0 = reinterpret_cast<uint32_t*>(Olo + g0*DD);
            uint32_t* L1 = reinterpret_cast<uint32_t*>(Olo + g1*DD);
            int cb = lane & 3;
            #pragma unroll
            for (int nf = 0; nf < 16; nf++) {
                int f2 = ni*64 + nf*4 + cb;
                float x0 = oacc[m2][nf][0]*mf0, x1 = oacc[m2][nf][1]*mf0;
                float y0 = oacc[m2][nf][2]*mf1, y1 = oacc[m2][nf][3]*mf1;
                __half hx0,lx0,hx1,lx1,hy0,ly0,hy1,ly1;
                hsplit(x0,hx0,lx0); hsplit(x1,hx1,lx1);
                hsplit(y0,hy0,ly0); hsplit(y1,hy1,ly1);
                __half2 a2 = __halves2half2(hx0,hx1), b2 = __halves2half2(lx0,lx1);
                __half2 c2 = __halves2half2(hy0,hy1), d2 = __halves2half2(ly0,ly1);
                H0[f2] = *reinterpret_cast<uint32_t*>(&a2);
                L0[f2] = *reinterpret_cast<uint32_t*>(&b2);
                H1[f2] = *reinterpret_cast<uint32_t*>(&c2);
                L1[f2] = *reinterpret_cast<uint32_t*>(&d2);
            }
        }
    }
}

// ---------------------------------------------------------------------------
extern "C" void kernel_launch(void* const* d_in, const int* in_sizes, int n_in,
                              void* d_out, int out_size)
{
    const float* src = (const float*)d_in[0];
    const float* Wq  = (const float*)d_in[1];
    const float* bq  = (const float*)d_in[2];
    const float* Wk  = (const float*)d_in[3];
    const float* bk  = (const float*)d_in[4];
    const float* Wv  = (const float*)d_in[5];
    const float* bv  = (const float*)d_in[6];
    const float* Wo  = (const float*)d_in[7];
    const float* bo  = (const float*)d_in[8];
    float* out = (float*)d_out;

    __half *pSh,*pSl,*pWqh,*pWql,*pWkh,*pWkl,*pWvh,*pWvl,*pWoh,*pWol;
    __half *pQ,*pK,*pV,*pOh,*pOl;
    float *pq0,*pk0;
    cudaGetSymbolAddress((void**)&pSh, g_srcHi);
    cudaGetSymbolAddress((void**)&pSl, g_srcLo);
    cudaGetSymbolAddress((void**)&pWqh, g_WqHi);
    cudaGetSymbolAddress((void**)&pWql, g_WqLo);
    cudaGetSymbolAddress((void**)&pWkh, g_WkHi);
    cudaGetSymbolAddress((void**)&pWkl, g_WkLo);
    cudaGetSymbolAddress((void**)&pWvh, g_WvHi);
    cudaGetSymbolAddress((void**)&pWvl, g_WvLo);
    cudaGetSymbolAddress((void**)&pWoh, g_WoHi);
    cudaGetSymbolAddress((void**)&pWol, g_WoLo);
    cudaGetSymbolAddress((void**)&pQ, g_Qh);
    cudaGetSymbolAddress((void**)&pK, g_Kh);
    cudaGetSymbolAddress((void**)&pV, g_Vth);
    cudaGetSymbolAddress((void**)&pOh, g_Ohi);
    cudaGetSymbolAddress((void**)&pOl, g_Olo);
    cudaGetSymbolAddress((void**)&pq0, g_q0);
    cudaGetSymbolAddress((void**)&pk0, g_k0);

    // splits
    split_kernel<<<(NN*DD/4 + 255)/256, 256>>>((const float4*)src, (uint2*)pSh, (uint2*)pSl, NN*DD/4);
    split_kernel<<<(DD*DD/4 + 255)/256, 256>>>((const float4*)Wq, (uint2*)pWqh, (uint2*)pWql, DD*DD/4);
    split_kernel<<<(DD*DD/4 + 255)/256, 256>>>((const float4*)Wk, (uint2*)pWkh, (uint2*)pWkl, DD*DD/4);
    split_kernel<<<(DD*DD/4 + 255)/256, 256>>>((const float4*)Wv, (uint2*)pWvh, (uint2*)pWvl, DD*DD/4);
    split_kernel<<<(DD*DD/4 + 255)/256, 256>>>((const float4*)Wo, (uint2*)pWoh, (uint2*)pWol, DD*DD/4);

    cudaFuncSetAttribute(proj_mma, cudaFuncAttributeMaxDynamicSharedMemorySize, PJ_SMEM);
    dim3 pg(NN/128, DD/128);   // (128, 2)
    proj_mma<<<pg, 256, PJ_SMEM>>>(pSh, pSl, pWqh, pWql, bq, pQ, nullptr, pq0, 0, 0.0625f);
    proj_mma<<<pg, 256, PJ_SMEM>>>(pSh, pSl, pWkh, pWkl, bk, pK, nullptr, pk0, 0, 1.0f);
    proj_mma<<<pg, 256, PJ_SMEM>>>(pSh, pSl, pWvh, pWvl, bv, pV, nullptr, nullptr, 2, 1.0f);

    cudaFuncSetAttribute(flash_mma, cudaFuncAttributeMaxDynamicSharedMemorySize, FL_SMEM);
    flash_mma<<<dim3(SS/128, BB), 256, FL_SMEM>>>(pQ, pK, pV, pq0, pk0, pOh, pOl);

    proj_mma<<<pg, 256, PJ_SMEM>>>(pOh, pOl, pWoh, pWol, bo, nullptr, out, nullptr, 3, 1.0f);
}

// round 7
// speedup vs baseline: 9.8707x; 1.1698x over previous
#include <cuda_runtime.h>
#include <cuda_fp16.h>
#include <cstdint>

#define BB 4
#define SS 4096
#define DD 256
#define NN (BB*SS)

// ---------------- device scratch ----------------
__device__ __half g_src16[NN*DD];
__device__ __half g_Wq16[DD*DD];
__device__ __half g_Wk16[DD*DD];
__device__ __half g_Wv16[DD*DD];
__device__ __half g_Wo16[DD*DD];
__device__ __half g_Qh[NN*DD];
__device__ __half g_Kh[NN*DD];
__device__ __half g_Vth[NN*DD];   // [b][d][s]
__device__ __half g_O16[NN*DD];
__device__ float g_q0[NN];
__device__ float g_k0[NN];

// ---------------- helpers ----------------
#define SWZ(o) ((o) ^ (((o) >> 3) & 0x70))

__device__ __forceinline__ uint32_t smem_u32(const void* p){
    uint32_t a;
    asm("{ .reg .u64 t; cvta.to.shared.u64 t, %1; cvt.u32.u64 %0, t; }" : "=r"(a) : "l"(p));
    return a;
}
__device__ __forceinline__ void sts32(uint32_t a, uint32_t v){
    asm volatile("st.shared.b32 [%0], %1;" :: "r"(a), "r"(v) : "memory");
}
__device__ __forceinline__ void cpa16(uint32_t s, const void* g){
    asm volatile("cp.async.cg.shared.global [%0], [%1], 16;" :: "r"(s), "l"(g) : "memory");
}
#define CPA_COMMIT() asm volatile("cp.async.commit_group;" ::: "memory")
#define CPA_WAIT(n)  asm volatile("cp.async.wait_group %0;" :: "n"(n) : "memory")

#define LDMX4(d0,d1,d2,d3,a) \
    asm volatile("ldmatrix.sync.aligned.m8n8.x4.shared.b16 {%0,%1,%2,%3}, [%4];" \
                 : "=r"(d0),"=r"(d1),"=r"(d2),"=r"(d3) : "r"(a))
#define MMA16816(c,a0,a1,a2,a3,b0,b1) \
    asm volatile("mma.sync.aligned.m16n8k16.row.col.f32.f16.f16.f32 " \
                 "{%0,%1,%2,%3},{%4,%5,%6,%7},{%8,%9},{%0,%1,%2,%3};" \
                 : "+f"((c)[0]),"+f"((c)[1]),"+f"((c)[2]),"+f"((c)[3]) \
                 : "r"(a0),"r"(a1),"r"(a2),"r"(a3),"r"(b0),"r"(b1))

// blocked-atom swizzled smem address of 16B chunk (r, c16); apg = atoms per 8-row group
__device__ __forceinline__ uint32_t tadr(uint32_t base, int r, int c16, int apg){
    return base + (uint32_t)(((((r>>3)*apg + (c16>>3))<<10)) +
                             SWZ((uint32_t)(((r&7)<<7) | ((c16&7)<<4))));
}

// ---------------------------------------------------------------------------
// cvt_kernel: fp32 -> fp16 single, float4 granularity
// ---------------------------------------------------------------------------
__global__ __launch_bounds__(256) void cvt_kernel(
    const float4* __restrict__ in, uint2* __restrict__ out, int n4)
{
    int i = blockIdx.x * 256 + threadIdx.x;
    if (i >= n4) return;
    float4 v = in[i];
    __half2 h01 = __floats2half2_rn(v.x, v.y);
    __half2 h23 = __floats2half2_rn(v.z, v.w);
    out[i] = make_uint2(*reinterpret_cast<uint32_t*>(&h01),
                        *reinterpret_cast<uint32_t*>(&h23));
}

// ---------------------------------------------------------------------------
// proj1: C = A W^T + bias, single fp16 MMA, fp32 accumulate.
// CTA 128x128, 8 warps (4M x 2N). Full K=256 resident in smem (no k-loop).
// mode 0: outH fp16 (val*scale) row-major + col0 fp32
// mode 2: outH fp16 transposed [b][d][s]
// mode 3: outF fp32 row-major
// ---------------------------------------------------------------------------
#define PJ_SMEM (131072 + 1024)

__global__ __launch_bounds__(256, 1) void proj1(
    const __half* __restrict__ A16, const __half* __restrict__ W16,
    const float* __restrict__ bias,
    __half* __restrict__ outH, float* __restrict__ outF,
    float* __restrict__ col0, int mode, float scale)
{
    extern __shared__ char psm[];
    const uint32_t raw = smem_u32(psm);
    const uint32_t abase = (raw + 1023u) & ~1023u;
    char* cbase = psm + (abase - raw);
    const uint32_t aA = abase, aW = abase + 65536u;

    const int tid = threadIdx.x, wid = tid >> 5, lane = tid & 31;
    const int mi = wid >> 1, ni = wid & 1;
    const int i0 = blockIdx.x * 128, j0 = blockIdx.y * 128;

    const int mat = lane >> 3, lr = lane & 7;
    const int arow = (mat & 1) * 8 + lr;
    const int asel = mat >> 1;
    const int brow = ((mat >> 1) << 3) + lr;
    const int bsel = mat & 1;

    const uint4* A4 = reinterpret_cast<const uint4*>(A16);
    const uint4* W4 = reinterpret_cast<const uint4*>(W16);

    #pragma unroll
    for (int t = 0; t < 16; t++) {
        int idx = tid + t * 256;          // 0..4095
        int r = idx >> 5, c = idx & 31;
        cpa16(tadr(aA, r, c, 4), A4 + (size_t)(i0 + r)*32 + c);
        cpa16(tadr(aW, r, c, 4), W4 + (size_t)(j0 + r)*32 + c);
    }
    CPA_COMMIT();

    float oacc[2][8][4];
    #pragma unroll
    for (int m2 = 0; m2 < 2; m2++)
        #pragma unroll
        for (int nf = 0; nf < 8; nf++)
            #pragma unroll
            for (int j = 0; j < 4; j++) oacc[m2][nf][j] = 0.0f;

    CPA_WAIT(0);
    __syncthreads();

    #pragma unroll 4
    for (int ks = 0; ks < 16; ks++) {
        uint32_t a[2][4];
        #pragma unroll
        for (int m2 = 0; m2 < 2; m2++)
            LDMX4(a[m2][0],a[m2][1],a[m2][2],a[m2][3],
                  tadr(aA, mi*32 + m2*16 + arow, 2*ks + asel, 4));
        #pragma unroll
        for (int n16 = 0; n16 < 4; n16++) {
            uint32_t b0,b1,b2,b3;
            LDMX4(b0,b1,b2,b3, tadr(aW, ni*64 + n16*16 + brow, 2*ks + bsel, 4));
            #pragma unroll
            for (int m2 = 0; m2 < 2; m2++) {
                MMA16816(oacc[m2][n16*2  ], a[m2][0],a[m2][1],a[m2][2],a[m2][3], b0,b1);
                MMA16816(oacc[m2][n16*2+1], a[m2][0],a[m2][1],a[m2][2],a[m2][3], b2,b3);
            }
        }
    }

    const int r0 = lane >> 2, cb = lane & 3;

    if (mode == 2) {
        // stage fp32 tile (128x129), then transposed coalesced fp16 write
        __syncthreads();
        float* st = reinterpret_cast<float*>(cbase);
        #pragma unroll
        for (int m2 = 0; m2 < 2; m2++)
            #pragma unroll
            for (int nf = 0; nf < 8; nf++) {
                int r = mi*32 + m2*16 + r0;
                int c = ni*64 + nf*8 + cb*2;
                float b0v = bias[j0 + c], b1v = bias[j0 + c + 1];
                st[r*129 + c]       = oacc[m2][nf][0] + b0v;
                st[r*129 + c + 1]   = oacc[m2][nf][1] + b1v;
                st[(r+8)*129 + c]   = oacc[m2][nf][2] + b0v;
                st[(r+8)*129 + c+1] = oacc[m2][nf][3] + b1v;
            }
        __syncthreads();
        const int b = i0 >> 12, s0 = i0 & 4095;
        uint4* V4o = reinterpret_cast<uint4*>(outH);
        #pragma unroll
        for (int t = 0; t < 8; t++) {
            int idx = tid + t * 256;      // 0..2047
            int dl = idx >> 4, sc = idx & 15;
            uint32_t hh[4];
            #pragma unroll
            for (int e = 0; e < 4; e++) {
                __half2 h2 = __floats2half2_rn(st[(sc*8 + 2*e)*129 + dl],
                                               st[(sc*8 + 2*e + 1)*129 + dl]);
                hh[e] = *reinterpret_cast<uint32_t*>(&h2);
            }
            V4o[((size_t)(b*DD + j0 + dl))*512 + (s0 >> 3) + sc] =
                make_uint4(hh[0], hh[1], hh[2], hh[3]);
        }
        return;
    }

    #pragma unroll
    for (int m2 = 0; m2 < 2; m2++)
        #pragma unroll
        for (int nf = 0; nf < 8; nf++) {
            int r = mi*32 + m2*16 + r0;
            int c = ni*64 + nf*8 + cb*2;
            float b0v = bias[j0 + c], b1v = bias[j0 + c + 1];
            float v00 = oacc[m2][nf][0] + b0v, v01 = oacc[m2][nf][1] + b1v;
            float v10 = oacc[m2][nf][2] + b0v, v11 = oacc[m2][nf][3] + b1v;
            size_t n0 = (size_t)(i0 + r), n1 = n0 + 8;
            if (mode == 0) {
                if (col0 && j0 + c == 0) { col0[n0] = v00; col0[n1] = v10; }
                __half2 a2 = __floats2half2_rn(v00*scale, v01*scale);
                __half2 c2 = __floats2half2_rn(v10*scale, v11*scale);
                reinterpret_cast<uint32_t*>(outH)[(n0*DD + j0 + c) >> 1] =
                    *reinterpret_cast<uint32_t*>(&a2);
                reinterpret_cast<uint32_t*>(outH)[(n1*DD + j0 + c) >> 1] =
                    *reinterpret_cast<uint32_t*>(&c2);
            } else {   // mode 3
                reinterpret_cast<float2*>(outF)[(n0*DD + j0 + c) >> 1] = make_float2(v00, v01);
                reinterpret_cast<float2*>(outF)[(n1*DD + j0 + c) >> 1] = make_float2(v10, v11);
            }
        }
}

// ---------------------------------------------------------------------------
// flash_mma: single-fp16 mma.sync flash attention, cp.async double-buffered.
// Writes O as single fp16.
// ---------------------------------------------------------------------------
#define OFF_Q    0u
#define OFF_K0   65536u
#define OFF_K1   98304u
#define OFF_V0   131072u
#define OFF_V1   163840u
#define OFF_P    196608u
#define FL_SMEM  (212992 + 1024)

__global__ __launch_bounds__(256, 1) void flash_mma(
    const __half* __restrict__ Qh_, const __half* __restrict__ Kh_,
    const __half* __restrict__ Vth_,
    const float* __restrict__ q0g, const float* __restrict__ k0g,
    __half* __restrict__ O16)
{
    extern __shared__ char fsm[];
    const uint32_t raw = smem_u32(fsm);
    const uint32_t abase = (raw + 1023u) & ~1023u;
    char* cbase = fsm + (abase - raw);
    const uint32_t aQ = abase + OFF_Q;
    const uint32_t aK[2] = { abase + OFF_K0, abase + OFF_K1 };
    const uint32_t aV[2] = { abase + OFF_V0, abase + OFF_V1 };
    const uint32_t aP = abase + OFF_P;

    const int tid = threadIdx.x, wid = tid >> 5, lane = tid & 31;
    const int mi = wid >> 1, ni = wid & 1;
    const int b = blockIdx.y, i0 = blockIdx.x * 128;

    const int mat = lane >> 3, lr = lane & 7;
    const int arow = (mat & 1) * 8 + lr;
    const int asel = mat >> 1;
    const int brow = ((mat >> 1) << 3) + lr;
    const int bsel = mat & 1;

    const uint4* Qg4 = reinterpret_cast<const uint4*>(Qh_) + ((size_t)(b*SS + i0)) * 32;
    const uint4* Kg4 = reinterpret_cast<const uint4*>(Kh_) + (size_t)b*SS*32;
    const uint4* Vg4 = reinterpret_cast<const uint4*>(Vth_) + (size_t)b*DD*512;

    #pragma unroll
    for (int t = 0; t < 16; t++) {
        int idx = tid + t * 256;
        int r = idx >> 5, c = idx & 31;
        cpa16(tadr(aQ, r, c, 4), Qg4 + (size_t)r*32 + c);
    }
    CPA_COMMIT();
    #pragma unroll
    for (int t = 0; t < 8; t++) {
        int idx = tid + t * 256;
        int r = idx >> 5, c = idx & 31;
        cpa16(tadr(aK[0], r, c, 4), Kg4 + (size_t)r*32 + c);
    }
    CPA_COMMIT();
    #pragma unroll
    for (int t = 0; t < 8; t++) {
        int idx = tid + t * 256;
        int r = idx >> 3, c = idx & 7;
        cpa16(tadr(aV[0], r, c, 1), Vg4 + (size_t)r*512 + c);
    }
    CPA_COMMIT();

    float oacc[2][16][4];
    #pragma unroll
    for (int m2 = 0; m2 < 2; m2++)
        #pragma unroll
        for (int nf = 0; nf < 16; nf++)
            #pragma unroll
            for (int j = 0; j < 4; j++) oacc[m2][nf][j] = 0.0f;
    float lsum[2][2] = {{0.f,0.f},{0.f,0.f}};

    for (int kt = 0; kt < SS/64; kt++) {
        const int buf = kt & 1;
        __syncthreads();
        if (kt + 1 < SS/64) {
            const int nb = buf ^ 1;
            #pragma unroll
            for (int t = 0; t < 8; t++) {
                int idx = tid + t * 256;
                int r = idx >> 5, c = idx & 31;
                cpa16(tadr(aK[nb], r, c, 4), Kg4 + (size_t)((kt+1)*64 + r)*32 + c);
            }
            CPA_COMMIT();
            #pragma unroll
            for (int t = 0; t < 8; t++) {
                int idx = tid + t * 256;
                int r = idx >> 3, c = idx & 7;
                cpa16(tadr(aV[nb], r, c, 1), Vg4 + (size_t)r*512 + (kt+1)*8 + c);
            }
            CPA_COMMIT();
            CPA_WAIT(2);
        } else {
            CPA_WAIT(0);
        }
        __syncthreads();

        // ---- MMA1: S = Q K^T (warp tile 32x32) ----
        float sacc[2][4][4];
        #pragma unroll
        for (int m2 = 0; m2 < 2; m2++)
            #pragma unroll
            for (int nf = 0; nf < 4; nf++)
                #pragma unroll
                for (int j = 0; j < 4; j++) sacc[m2][nf][j] = 0.0f;

        #pragma unroll 4
        for (int ks = 0; ks < 16; ks++) {
            uint32_t a[2][4];
            #pragma unroll
            for (int m2 = 0; m2 < 2; m2++)
                LDMX4(a[m2][0],a[m2][1],a[m2][2],a[m2][3],
                      tadr(aQ, mi*32 + m2*16 + arow, 2*ks + asel, 4));
            #pragma unroll
            for (int n16 = 0; n16 < 2; n16++) {
                uint32_t b0,b1,b2,b3;
                LDMX4(b0,b1,b2,b3,
                      tadr(aK[buf], ni*32 + n16*16 + brow, 2*ks + bsel, 4));
                #pragma unroll
                for (int m2 = 0; m2 < 2; m2++) {
                    MMA16816(sacc[m2][n16*2  ], a[m2][0],a[m2][1],a[m2][2],a[m2][3], b0,b1);
                    MMA16816(sacc[m2][n16*2+1], a[m2][0],a[m2][1],a[m2][2],a[m2][3], b2,b3);
                }
            }
        }

        // ---- softmax (no max-sub) -> P fp16 ----
        {
            const int r0 = lane >> 2;
            const int ib = (lane & 3) * 4;
            #pragma unroll
            for (int m2 = 0; m2 < 2; m2++) {
                #pragma unroll
                for (int nf = 0; nf < 4; nf++) {
                    float e0 = __expf(sacc[m2][nf][0]);
                    float e1 = __expf(sacc[m2][nf][1]);
                    float e2 = __expf(sacc[m2][nf][2]);
                    float e3 = __expf(sacc[m2][nf][3]);
                    lsum[m2][0] += e0 + e1;
                    lsum[m2][1] += e2 + e3;
                    __half2 h01 = __floats2half2_rn(e0, e1);
                    __half2 h23 = __floats2half2_rn(e2, e3);
                    int row = mi*32 + m2*16 + r0;
                    sts32(tadr(aP, row,     ni*4 + nf, 1) + ib,
                          *reinterpret_cast<uint32_t*>(&h01));
                    sts32(tadr(aP, row + 8, ni*4 + nf, 1) + ib,
                          *reinterpret_cast<uint32_t*>(&h23));
                }
            }
        }
        // pair barrier: only the 2 warps sharing rows mi*32..+32 exchange P
        asm volatile("bar.sync %0, %1;" :: "r"(mi + 1), "r"(64) : "memory");

        // ---- MMA2: O += P V (warp tile 32x128) ----
        #pragma unroll
        for (int ks = 0; ks < 4; ks++) {
            uint32_t a[2][4];
            #pragma unroll
            for (int m2 = 0; m2 < 2; m2++)
                LDMX4(a[m2][0],a[m2][1],a[m2][2],a[m2][3],
                      tadr(aP, mi*32 + m2*16 + arow, 2*ks + asel, 1));
            #pragma unroll
            for (int n16 = 0; n16 < 8; n16++) {
                uint32_t b0,b1,b2,b3;
                LDMX4(b0,b1,b2,b3,
                      tadr(aV[buf], ni*128 + n16*16 + brow, 2*ks + bsel, 1));
                #pragma unroll
                for (int m2 = 0; m2 < 2; m2++) {
                    MMA16816(oacc[m2][n16*2  ], a[m2][0],a[m2][1],a[m2][2],a[m2][3], b0,b1);
                    MMA16816(oacc[m2][n16*2+1], a[m2][0],a[m2][1],a[m2][2],a[m2][3], b2,b3);
                }
            }
        }
    }

    // ---- epilogue: combine lsum across ni pairs, mask, normalize, fp16 store ----
    __syncthreads();
    float* Lsh = reinterpret_cast<float*>(cbase + OFF_P);
    {
        const int r0 = lane >> 2;
        #pragma unroll
        for (int m2 = 0; m2 < 2; m2++)
            #pragma unroll
            for (int h = 0; h < 2; h++) {
                float v = lsum[m2][h];
                v += __shfl_xor_sync(0xffffffff, v, 1);
                v += __shfl_xor_sync(0xffffffff, v, 2);
                if ((lane & 3) == 0)
                    Lsh[(mi*32 + m2*16 + h*8 + r0)*2 + ni] = v;
            }
    }
    __syncthreads();
    {
        const int r0 = lane >> 2;
        #pragma unroll
        for (int m2 = 0; m2 < 2; m2++) {
            int row0 = mi*32 + m2*16 + r0;
            size_t g0 = (size_t)b*SS + i0 + row0;
            size_t g1 = g0 + 8;
            float l0 = Lsh[row0*2] + Lsh[row0*2 + 1];
            float l1 = Lsh[(row0+8)*2] + Lsh[(row0+8)*2 + 1];
            float mf0 = (q0g[g0] != 0.0f && k0g[g0] != 0.0f) ? (1.0f / l0) : 0.0f;
            float mf1 = (q0g[g1] != 0.0f && k0g[g1] != 0.0f) ? (1.0f / l1) : 0.0f;
            uint32_t* H0 = reinterpret_cast<uint32_t*>(O16 + g0*DD);
            uint32_t* H1 = reinterpret_cast<uint32_t*>(O16 + g1*DD);
            int cb = lane & 3;
            #pragma unroll
            for (int nf = 0; nf < 16; nf++) {
                int f2 = ni*64 + nf*4 + cb;
                __half2 a2 = __floats2half2_rn(oacc[m2][nf][0]*mf0, oacc[m2][nf][1]*mf0);
                __half2 c2 = __floats2half2_rn(oacc[m2][nf][2]*mf1, oacc[m2][nf][3]*mf1);
                H0[f2] = *reinterpret_cast<uint32_t*>(&a2);
                H1[f2] = *reinterpret_cast<uint32_t*>(&c2);
            }
        }
    }
}

// ---------------------------------------------------------------------------
extern "C" void kernel_launch(void* const* d_in, const int* in_sizes, int n_in,
                              void* d_out, int out_size)
{
    const float* src = (const float*)d_in[0];
    const float* Wq  = (const float*)d_in[1];
    const float* bq  = (const float*)d_in[2];
    const float* Wk  = (const float*)d_in[3];
    const float* bk  = (const float*)d_in[4];
    const float* Wv  = (const float*)d_in[5];
    const float* bv  = (const float*)d_in[6];
    const float* Wo  = (const float*)d_in[7];
    const float* bo  = (const float*)d_in[8];
    float* out = (float*)d_out;

    __half *pS,*pWq,*pWk,*pWv,*pWo,*pQ,*pK,*pV,*pO;
    float *pq0,*pk0;
    cudaGetSymbolAddress((void**)&pS, g_src16);
    cudaGetSymbolAddress((void**)&pWq, g_Wq16);
    cudaGetSymbolAddress((void**)&pWk, g_Wk16);
    cudaGetSymbolAddress((void**)&pWv, g_Wv16);
    cudaGetSymbolAddress((void**)&pWo, g_Wo16);
    cudaGetSymbolAddress((void**)&pQ, g_Qh);
    cudaGetSymbolAddress((void**)&pK, g_Kh);
    cudaGetSymbolAddress((void**)&pV, g_Vth);
    cudaGetSymbolAddress((void**)&pO, g_O16);
    cudaGetSymbolAddress((void**)&pq0, g_q0);
    cudaGetSymbolAddress((void**)&pk0, g_k0);

    cvt_kernel<<<(NN*DD/4 + 255)/256, 256>>>((const float4*)src, (uint2*)pS, NN*DD/4);
    cvt_kernel<<<(DD*DD/4 + 255)/256, 256>>>((const float4*)Wq, (uint2*)pWq, DD*DD/4);
    cvt_kernel<<<(DD*DD/4 + 255)/256, 256>>>((const float4*)Wk, (uint2*)pWk, DD*DD/4);
    cvt_kernel<<<(DD*DD/4 + 255)/256, 256>>>((const float4*)Wv, (uint2*)pWv, DD*DD/4);
    cvt_kernel<<<(DD*DD/4 + 255)/256, 256>>>((const float4*)Wo, (uint2*)pWo, DD*DD/4);

    cudaFuncSetAttribute(proj1, cudaFuncAttributeMaxDynamicSharedMemorySize, PJ_SMEM);
    dim3 pg(NN/128, DD/128);   // (128, 2)
    proj1<<<pg, 256, PJ_SMEM>>>(pS, pWq, bq, pQ, nullptr, pq0, 0, 0.0625f);
    proj1<<<pg, 256, PJ_SMEM>>>(pS, pWk, bk, pK, nullptr, pk0, 0, 1.0f);
    proj1<<<pg, 256, PJ_SMEM>>>(pS, pWv, bv, pV, nullptr, nullptr, 2, 1.0f);

    cudaFuncSetAttribute(flash_mma, cudaFuncAttributeMaxDynamicSharedMemorySize, FL_SMEM);
    flash_mma<<<dim3(SS/128, BB), 256, FL_SMEM>>>(pQ, pK, pV, pq0, pk0, pO);

    proj1<<<pg, 256, PJ_SMEM>>>(pO, pWo, bo, nullptr, out, nullptr, 3, 1.0f);
}